// round 3
// baseline (speedup 1.0000x reference)
#include <cuda_runtime.h>
#include <math.h>

#define B_    8
#define N_    2048
#define FIN_  128
#define FOUT_ 64
#define BN_   (B_ * N_)

#define TI      128
#define TJ      64
#define JSPLIT  2
#define JCHUNK  (N_ / JSPLIT)

typedef unsigned long long u64;

__device__ __forceinline__ u64 pack2(float lo, float hi) {
    u64 r;
    asm("mov.b64 %0, {%1, %2};" : "=l"(r) : "f"(lo), "f"(hi));
    return r;
}
__device__ __forceinline__ void unpack2(u64 v, float& lo, float& hi) {
    asm("mov.b64 {%0, %1}, %2;" : "=f"(lo), "=f"(hi) : "l"(v));
}
__device__ __forceinline__ void ffma2(u64& d, u64 a, u64 b) {
    asm("fma.rn.f32x2 %0, %1, %2, %3;" : "=l"(d) : "l"(a), "l"(b), "l"(d));
}

// -------- scratch (device globals; no runtime allocation) --------
__device__ float g_h[BN_ * FOUT_];                 // 4 MB : h = x @ W
__device__ float g_s1[BN_], g_s2[BN_];
__device__ float g_E1[BN_], g_F1[BN_], g_E2[BN_], g_F2[BN_];
__device__ float g_acc[JSPLIT][BN_ * FOUT_];       // 8 MB : partial aggregations
__device__ float g_l[JSPLIT][BN_];                 // partial softmax denominators

// ============================================================================
// Kernel 1: h = x @ W + s1/s2 dots + per-node exps.
// 256 blocks x 128 threads, 64 rows/block, 2 rows/thread (occupancy fix).
// ============================================================================
__global__ __launch_bounds__(128) void k1_proj(const float* __restrict__ x,
                                               const float* __restrict__ W,
                                               const float* __restrict__ a) {
    __shared__ float sW[FIN_ * FOUT_];   // 32 KB
    __shared__ float sr1[64 * 4];
    __shared__ float sr2[64 * 4];

    const int t = threadIdx.x;
    {
        float4*       d = reinterpret_cast<float4*>(sW);
        const float4* s = reinterpret_cast<const float4*>(W);
        #pragma unroll
        for (int q = 0; q < 16; ++q) d[t + q * 128] = s[t + q * 128];
    }
    __syncthreads();

    const int fg = t >> 5;       // 0..3 : 16-col group of FOUT
    const int rt = t & 31;
    const int rowbase = blockIdx.x * 64;

    float acc[2][16];
    #pragma unroll
    for (int r = 0; r < 2; ++r)
        #pragma unroll
        for (int c = 0; c < 16; ++c) acc[r][c] = 0.f;

    const float4* x4 = reinterpret_cast<const float4*>(x);
    for (int k4 = 0; k4 < FIN_ / 4; ++k4) {
        float xs[2][4];
        #pragma unroll
        for (int rr = 0; rr < 2; ++rr) {
            float4 xv = x4[(size_t)(rowbase + rt + 32 * rr) * (FIN_ / 4) + k4];
            xs[rr][0] = xv.x; xs[rr][1] = xv.y; xs[rr][2] = xv.z; xs[rr][3] = xv.w;
        }
        #pragma unroll
        for (int q = 0; q < 4; ++q) {
            const int k = k4 * 4 + q;
            const float4* wr = reinterpret_cast<const float4*>(&sW[k * FOUT_ + fg * 16]);
            const float4 w0 = wr[0], w1 = wr[1], w2 = wr[2], w3 = wr[3];
            #pragma unroll
            for (int rr = 0; rr < 2; ++rr) {
                const float xv = xs[rr][q];
                acc[rr][0]  += xv * w0.x; acc[rr][1]  += xv * w0.y;
                acc[rr][2]  += xv * w0.z; acc[rr][3]  += xv * w0.w;
                acc[rr][4]  += xv * w1.x; acc[rr][5]  += xv * w1.y;
                acc[rr][6]  += xv * w1.z; acc[rr][7]  += xv * w1.w;
                acc[rr][8]  += xv * w2.x; acc[rr][9]  += xv * w2.y;
                acc[rr][10] += xv * w2.z; acc[rr][11] += xv * w2.w;
                acc[rr][12] += xv * w3.x; acc[rr][13] += xv * w3.y;
                acc[rr][14] += xv * w3.z; acc[rr][15] += xv * w3.w;
            }
        }
    }

    float a1v[16], a2v[16];
    #pragma unroll
    for (int f = 0; f < 16; ++f) {
        a1v[f] = a[fg * 16 + f];
        a2v[f] = a[FOUT_ + fg * 16 + f];
    }
    #pragma unroll
    for (int rr = 0; rr < 2; ++rr) {
        const int rloc = rt + 32 * rr;
        const size_t row = (size_t)rowbase + rloc;
        float4* hd = reinterpret_cast<float4*>(&g_h[row * FOUT_ + fg * 16]);
        #pragma unroll
        for (int f4 = 0; f4 < 4; ++f4)
            hd[f4] = make_float4(acc[rr][f4 * 4], acc[rr][f4 * 4 + 1],
                                 acc[rr][f4 * 4 + 2], acc[rr][f4 * 4 + 3]);
        float ps1 = 0.f, ps2 = 0.f;
        #pragma unroll
        for (int f = 0; f < 16; ++f) {
            ps1 += acc[rr][f] * a1v[f];
            ps2 += acc[rr][f] * a2v[f];
        }
        sr1[rloc * 4 + fg] = ps1;
        sr2[rloc * 4 + fg] = ps2;
    }
    __syncthreads();
    if (t < 64) {
        const int row = rowbase + t;
        const float s1 = sr1[t * 4] + sr1[t * 4 + 1] + sr1[t * 4 + 2] + sr1[t * 4 + 3];
        const float s2 = sr2[t * 4] + sr2[t * 4 + 1] + sr2[t * 4 + 2] + sr2[t * 4 + 3];
        g_s1[row] = s1;
        g_s2[row] = s2;
        g_E1[row] = expf(s1);
        g_F1[row] = expf(0.2f * s1);
        g_E2[row] = expf(s2);
        g_F2[row] = expf(0.2f * s2);
    }
}

// ============================================================================
// Kernel 2: fused masked attention + aggregation.
// Phase B uses packed fma.rn.f32x2 -> 2 lane-FMAs per fma-pipe slot.
// ============================================================================
__global__ __launch_bounds__(256) void k2_attn(const int* __restrict__ adj) {
    extern __shared__ float sm[];
    float* smH  = sm;                 // TJ*64   = 4096 floats
    float* smP  = sm + 4096;          // TJ*128  = 8192 floats (XOR-swizzled)
    float* s_s1 = smP + 8192;         // 128
    float* s_E1 = s_s1 + 128;
    float* s_F1 = s_E1 + 128;
    float* s_s2 = s_F1 + 128;         // 64
    float* s_E2 = s_s2 + 64;
    float* s_F2 = s_E2 + 64;

    const int t  = threadIdx.x;
    const int b  = blockIdx.y;
    const int i0 = blockIdx.x * TI;
    const int js = blockIdx.z;
    const int jbase = js * JCHUNK;
    const int nb = b * N_;

    if (t < TI) {
        const int g = nb + i0 + t;
        s_s1[t] = g_s1[g]; s_E1[t] = g_E1[g]; s_F1[t] = g_F1[g];
    }

    const int tf = t >> 5;            // warp id = f-group (8 cols each)
    const int ti = t & 31;            // i-group (4 rows each)
    const int f0 = tf * 8;

    u64 acc2[4][4];                   // [i-row][f-pair] packed f32x2
    #pragma unroll
    for (int r = 0; r < 4; ++r)
        #pragma unroll
        for (int c = 0; c < 4; ++c) acc2[r][c] = 0ull;
    float lacc[4] = {0.f, 0.f, 0.f, 0.f};

    const int j4  = t & 15;           // phase-A j quad
    const int ibA = t >> 4;           // phase-A i base

    for (int jt = 0; jt < JCHUNK; jt += TJ) {
        const int j0 = jbase + jt;
        __syncthreads();
        {   // load h tile [TJ][64]
            const float4* src = reinterpret_cast<const float4*>(&g_h[(size_t)(nb + j0) * FOUT_]);
            float4* dst = reinterpret_cast<float4*>(smH);
            #pragma unroll
            for (int q = 0; q < 4; ++q) dst[t + q * 256] = src[t + q * 256];
        }
        if (t < 64)        s_s2[t]       = g_s2[nb + j0 + t];
        else if (t < 128)  s_E2[t - 64]  = g_E2[nb + j0 + t - 64];
        else if (t < 192)  s_F2[t - 128] = g_F2[nb + j0 + t - 128];
        __syncthreads();

        // ---- Phase A: P tile into swizzled smem (no MUFU per pair) ----
        #pragma unroll
        for (int ii = 0; ii < 8; ++ii) {
            const int i = ibA + ii * 16;
            const float s1 = s_s1[i], E1 = s_E1[i], F1 = s_F1[i];
            const int4 aj = *reinterpret_cast<const int4*>(
                adj + (size_t)(nb + i0 + i) * N_ + j0 + j4 * 4);
            const int jl = j4 * 4;
            const int av[4] = {aj.x, aj.y, aj.z, aj.w};
            #pragma unroll
            for (int q = 0; q < 4; ++q) {
                const int j = jl + q;
                const float xsum = s1 + s_s2[j];
                float p = (xsum > 0.f) ? (E1 * s_E2[j]) : (F1 * s_F2[j]);
                p = (av[q] > 0) ? p : 0.f;
                smP[j * 128 + (i ^ ((j & 31) << 2))] = p;
            }
        }
        __syncthreads();

        // ---- Phase B: packed-f32x2 register-tiled GEMM acc += P * H ----
        #pragma unroll 2
        for (int jj = 0; jj < TJ; ++jj) {
            const float4 pv = *reinterpret_cast<const float4*>(
                &smP[jj * 128 + ((ti * 4) ^ ((jj & 31) << 2))]);
            const float4 hA = *reinterpret_cast<const float4*>(&smH[jj * FOUT_ + f0]);
            const float4 hB = *reinterpret_cast<const float4*>(&smH[jj * FOUT_ + f0 + 4]);
            u64 h2[4];
            h2[0] = pack2(hA.x, hA.y); h2[1] = pack2(hA.z, hA.w);
            h2[2] = pack2(hB.x, hB.y); h2[3] = pack2(hB.z, hB.w);
            u64 pd[4];
            pd[0] = pack2(pv.x, pv.x); pd[1] = pack2(pv.y, pv.y);
            pd[2] = pack2(pv.z, pv.z); pd[3] = pack2(pv.w, pv.w);
            #pragma unroll
            for (int r = 0; r < 4; ++r)
                #pragma unroll
                for (int c = 0; c < 4; ++c)
                    ffma2(acc2[r][c], pd[r], h2[c]);
            if (tf == 0) {   // warp-uniform: warp 0 carries softmax denominator
                lacc[0] += pv.x; lacc[1] += pv.y; lacc[2] += pv.z; lacc[3] += pv.w;
            }
        }
    }

    // write partials
    #pragma unroll
    for (int r = 0; r < 4; ++r) {
        const size_t row = (size_t)nb + i0 + ti * 4 + r;
        float av[8];
        #pragma unroll
        for (int c = 0; c < 4; ++c) unpack2(acc2[r][c], av[2 * c], av[2 * c + 1]);
        float4* dst = reinterpret_cast<float4*>(&g_acc[js][row * FOUT_ + f0]);
        dst[0] = make_float4(av[0], av[1], av[2], av[3]);
        dst[1] = make_float4(av[4], av[5], av[6], av[7]);
    }
    if (tf == 0) {
        #pragma unroll
        for (int r = 0; r < 4; ++r)
            g_l[js][nb + i0 + ti * 4 + r] = lacc[r];
    }
}

// ============================================================================
// Kernel 3: combine j-splits, normalize, LayerNorm, ELU.  One warp per row.
// ============================================================================
__global__ __launch_bounds__(256) void k3_ln(const float* __restrict__ gamma,
                                             const float* __restrict__ beta,
                                             float* __restrict__ out) {
    const int t = threadIdx.x;
    const int warp = t >> 5, lane = t & 31;
    const int row = blockIdx.x * 8 + warp;
    const size_t base = (size_t)row * FOUT_;

    const float v0 = g_acc[0][base + lane]      + g_acc[1][base + lane];
    const float v1 = g_acc[0][base + 32 + lane] + g_acc[1][base + 32 + lane];
    const float l  = g_l[0][row] + g_l[1][row];
    const float inv = 1.f / l;
    const float h0 = v0 * inv, h1 = v1 * inv;

    float s = h0 + h1;
    #pragma unroll
    for (int o = 16; o; o >>= 1) s += __shfl_xor_sync(0xffffffffu, s, o);
    const float mu = s * (1.f / 64.f);

    const float d0 = h0 - mu, d1 = h1 - mu;
    float vs = d0 * d0 + d1 * d1;
    #pragma unroll
    for (int o = 16; o; o >>= 1) vs += __shfl_xor_sync(0xffffffffu, vs, o);
    const float rstd = rsqrtf(vs * (1.f / 64.f) + 1e-5f);

    const float y0 = d0 * rstd * gamma[lane]      + beta[lane];
    const float y1 = d1 * rstd * gamma[lane + 32] + beta[lane + 32];
    out[base + lane]      = (y0 > 0.f) ? y0 : expm1f(y0);
    out[base + 32 + lane] = (y1 > 0.f) ? y1 : expm1f(y1);
}

// ============================================================================
extern "C" void kernel_launch(void* const* d_in, const int* in_sizes, int n_in,
                              void* d_out, int out_size) {
    const float* x     = (const float*)d_in[0];
    const int*   adj   = (const int*)  d_in[1];
    const float* W     = (const float*)d_in[2];
    const float* a     = (const float*)d_in[3];
    const float* gamma = (const float*)d_in[4];
    const float* beta  = (const float*)d_in[5];
    float* out = (float*)d_out;

    const int smem2 = (4096 + 8192 + 3 * 128 + 3 * 64) * (int)sizeof(float); // 51456 B
    cudaFuncSetAttribute(k2_attn, cudaFuncAttributeMaxDynamicSharedMemorySize, smem2);

    k1_proj<<<BN_ / 64, 128>>>(x, W, a);
    k2_attn<<<dim3(N_ / TI, B_, JSPLIT), 256, smem2>>>(adj);
    k3_ln<<<BN_ / 8, 256>>>(gamma, beta, out);
}

// round 4
// speedup vs baseline: 1.0005x; 1.0005x over previous
#include <cuda_runtime.h>
#include <math.h>

#define B_    8
#define N_    2048
#define FIN_  128
#define FOUT_ 64
#define BN_   (B_ * N_)

#define TI      128
#define TJ      64
#define JSPLIT  2
#define JCHUNK  (N_ / JSPLIT)

typedef unsigned long long u64;

__device__ __forceinline__ u64 pack2(float lo, float hi) {
    u64 r;
    asm("mov.b64 %0, {%1, %2};" : "=l"(r) : "f"(lo), "f"(hi));
    return r;
}
__device__ __forceinline__ void unpack2(u64 v, float& lo, float& hi) {
    asm("mov.b64 {%0, %1}, %2;" : "=f"(lo), "=f"(hi) : "l"(v));
}
__device__ __forceinline__ void ffma2(u64& d, u64 a, u64 b) {
    asm("fma.rn.f32x2 %0, %1, %2, %3;" : "=l"(d) : "l"(a), "l"(b), "l"(d));
}

// -------- scratch (device globals; no runtime allocation) --------
__device__ float g_h[BN_ * FOUT_];                 // 4 MB : h = x @ W
__device__ float g_s1[BN_], g_s2[BN_];
__device__ float g_E1[BN_], g_F1[BN_], g_E2[BN_], g_F2[BN_];
__device__ float g_acc[JSPLIT][BN_ * FOUT_];       // 8 MB : partial aggregations
__device__ float g_l[JSPLIT][BN_];                 // partial softmax denominators

// ============================================================================
// Kernel 1: h = x @ W + s1/s2 dots + per-node exps.
// 256 blocks x 128 threads, 64 rows/block, 2 rows/thread (occupancy fix).
// ============================================================================
__global__ __launch_bounds__(128) void k1_proj(const float* __restrict__ x,
                                               const float* __restrict__ W,
                                               const float* __restrict__ a) {
    __shared__ float sW[FIN_ * FOUT_];   // 32 KB
    __shared__ float sr1[64 * 4];
    __shared__ float sr2[64 * 4];

    const int t = threadIdx.x;
    {
        float4*       d = reinterpret_cast<float4*>(sW);
        const float4* s = reinterpret_cast<const float4*>(W);
        #pragma unroll
        for (int q = 0; q < 16; ++q) d[t + q * 128] = s[t + q * 128];
    }
    __syncthreads();

    const int fg = t >> 5;       // 0..3 : 16-col group of FOUT
    const int rt = t & 31;
    const int rowbase = blockIdx.x * 64;

    float acc[2][16];
    #pragma unroll
    for (int r = 0; r < 2; ++r)
        #pragma unroll
        for (int c = 0; c < 16; ++c) acc[r][c] = 0.f;

    const float4* x4 = reinterpret_cast<const float4*>(x);
    for (int k4 = 0; k4 < FIN_ / 4; ++k4) {
        float xs[2][4];
        #pragma unroll
        for (int rr = 0; rr < 2; ++rr) {
            float4 xv = x4[(size_t)(rowbase + rt + 32 * rr) * (FIN_ / 4) + k4];
            xs[rr][0] = xv.x; xs[rr][1] = xv.y; xs[rr][2] = xv.z; xs[rr][3] = xv.w;
        }
        #pragma unroll
        for (int q = 0; q < 4; ++q) {
            const int k = k4 * 4 + q;
            const float4* wr = reinterpret_cast<const float4*>(&sW[k * FOUT_ + fg * 16]);
            const float4 w0 = wr[0], w1 = wr[1], w2 = wr[2], w3 = wr[3];
            #pragma unroll
            for (int rr = 0; rr < 2; ++rr) {
                const float xv = xs[rr][q];
                acc[rr][0]  += xv * w0.x; acc[rr][1]  += xv * w0.y;
                acc[rr][2]  += xv * w0.z; acc[rr][3]  += xv * w0.w;
                acc[rr][4]  += xv * w1.x; acc[rr][5]  += xv * w1.y;
                acc[rr][6]  += xv * w1.z; acc[rr][7]  += xv * w1.w;
                acc[rr][8]  += xv * w2.x; acc[rr][9]  += xv * w2.y;
                acc[rr][10] += xv * w2.z; acc[rr][11] += xv * w2.w;
                acc[rr][12] += xv * w3.x; acc[rr][13] += xv * w3.y;
                acc[rr][14] += xv * w3.z; acc[rr][15] += xv * w3.w;
            }
        }
    }

    float a1v[16], a2v[16];
    #pragma unroll
    for (int f = 0; f < 16; ++f) {
        a1v[f] = a[fg * 16 + f];
        a2v[f] = a[FOUT_ + fg * 16 + f];
    }
    #pragma unroll
    for (int rr = 0; rr < 2; ++rr) {
        const int rloc = rt + 32 * rr;
        const size_t row = (size_t)rowbase + rloc;
        float4* hd = reinterpret_cast<float4*>(&g_h[row * FOUT_ + fg * 16]);
        #pragma unroll
        for (int f4 = 0; f4 < 4; ++f4)
            hd[f4] = make_float4(acc[rr][f4 * 4], acc[rr][f4 * 4 + 1],
                                 acc[rr][f4 * 4 + 2], acc[rr][f4 * 4 + 3]);
        float ps1 = 0.f, ps2 = 0.f;
        #pragma unroll
        for (int f = 0; f < 16; ++f) {
            ps1 += acc[rr][f] * a1v[f];
            ps2 += acc[rr][f] * a2v[f];
        }
        sr1[rloc * 4 + fg] = ps1;
        sr2[rloc * 4 + fg] = ps2;
    }
    __syncthreads();
    if (t < 64) {
        const int row = rowbase + t;
        const float s1 = sr1[t * 4] + sr1[t * 4 + 1] + sr1[t * 4 + 2] + sr1[t * 4 + 3];
        const float s2 = sr2[t * 4] + sr2[t * 4 + 1] + sr2[t * 4 + 2] + sr2[t * 4 + 3];
        g_s1[row] = s1;
        g_s2[row] = s2;
        g_E1[row] = expf(s1);
        g_F1[row] = expf(0.2f * s1);
        g_E2[row] = expf(s2);
        g_F2[row] = expf(0.2f * s2);
    }
}

// ============================================================================
// Kernel 2: fused masked attention + aggregation.
// Phase B uses packed fma.rn.f32x2 -> 2 lane-FMAs per fma-pipe slot.
// ============================================================================
__global__ __launch_bounds__(256) void k2_attn(const int* __restrict__ adj) {
    extern __shared__ float sm[];
    float* smH  = sm;                 // TJ*64   = 4096 floats
    float* smP  = sm + 4096;          // TJ*128  = 8192 floats (XOR-swizzled)
    float* s_s1 = smP + 8192;         // 128
    float* s_E1 = s_s1 + 128;
    float* s_F1 = s_E1 + 128;
    float* s_s2 = s_F1 + 128;         // 64
    float* s_E2 = s_s2 + 64;
    float* s_F2 = s_E2 + 64;

    const int t  = threadIdx.x;
    const int b  = blockIdx.y;
    const int i0 = blockIdx.x * TI;
    const int js = blockIdx.z;
    const int jbase = js * JCHUNK;
    const int nb = b * N_;

    if (t < TI) {
        const int g = nb + i0 + t;
        s_s1[t] = g_s1[g]; s_E1[t] = g_E1[g]; s_F1[t] = g_F1[g];
    }

    const int tf = t >> 5;            // warp id = f-group (8 cols each)
    const int ti = t & 31;            // i-group (4 rows each)
    const int f0 = tf * 8;

    u64 acc2[4][4];                   // [i-row][f-pair] packed f32x2
    #pragma unroll
    for (int r = 0; r < 4; ++r)
        #pragma unroll
        for (int c = 0; c < 4; ++c) acc2[r][c] = 0ull;
    float lacc[4] = {0.f, 0.f, 0.f, 0.f};

    const int j4  = t & 15;           // phase-A j quad
    const int ibA = t >> 4;           // phase-A i base

    for (int jt = 0; jt < JCHUNK; jt += TJ) {
        const int j0 = jbase + jt;
        __syncthreads();
        {   // load h tile [TJ][64]
            const float4* src = reinterpret_cast<const float4*>(&g_h[(size_t)(nb + j0) * FOUT_]);
            float4* dst = reinterpret_cast<float4*>(smH);
            #pragma unroll
            for (int q = 0; q < 4; ++q) dst[t + q * 256] = src[t + q * 256];
        }
        if (t < 64)        s_s2[t]       = g_s2[nb + j0 + t];
        else if (t < 128)  s_E2[t - 64]  = g_E2[nb + j0 + t - 64];
        else if (t < 192)  s_F2[t - 128] = g_F2[nb + j0 + t - 128];
        __syncthreads();

        // ---- Phase A: P tile into swizzled smem (no MUFU per pair) ----
        #pragma unroll
        for (int ii = 0; ii < 8; ++ii) {
            const int i = ibA + ii * 16;
            const float s1 = s_s1[i], E1 = s_E1[i], F1 = s_F1[i];
            const int4 aj = *reinterpret_cast<const int4*>(
                adj + (size_t)(nb + i0 + i) * N_ + j0 + j4 * 4);
            const int jl = j4 * 4;
            const int av[4] = {aj.x, aj.y, aj.z, aj.w};
            #pragma unroll
            for (int q = 0; q < 4; ++q) {
                const int j = jl + q;
                const float xsum = s1 + s_s2[j];
                float p = (xsum > 0.f) ? (E1 * s_E2[j]) : (F1 * s_F2[j]);
                p = (av[q] > 0) ? p : 0.f;
                smP[j * 128 + (i ^ ((j & 31) << 2))] = p;
            }
        }
        __syncthreads();

        // ---- Phase B: packed-f32x2 register-tiled GEMM acc += P * H ----
        #pragma unroll 2
        for (int jj = 0; jj < TJ; ++jj) {
            const float4 pv = *reinterpret_cast<const float4*>(
                &smP[jj * 128 + ((ti * 4) ^ ((jj & 31) << 2))]);
            const float4 hA = *reinterpret_cast<const float4*>(&smH[jj * FOUT_ + f0]);
            const float4 hB = *reinterpret_cast<const float4*>(&smH[jj * FOUT_ + f0 + 4]);
            u64 h2[4];
            h2[0] = pack2(hA.x, hA.y); h2[1] = pack2(hA.z, hA.w);
            h2[2] = pack2(hB.x, hB.y); h2[3] = pack2(hB.z, hB.w);
            u64 pd[4];
            pd[0] = pack2(pv.x, pv.x); pd[1] = pack2(pv.y, pv.y);
            pd[2] = pack2(pv.z, pv.z); pd[3] = pack2(pv.w, pv.w);
            #pragma unroll
            for (int r = 0; r < 4; ++r)
                #pragma unroll
                for (int c = 0; c < 4; ++c)
                    ffma2(acc2[r][c], pd[r], h2[c]);
            if (tf == 0) {   // warp-uniform: warp 0 carries softmax denominator
                lacc[0] += pv.x; lacc[1] += pv.y; lacc[2] += pv.z; lacc[3] += pv.w;
            }
        }
    }

    // write partials
    #pragma unroll
    for (int r = 0; r < 4; ++r) {
        const size_t row = (size_t)nb + i0 + ti * 4 + r;
        float av[8];
        #pragma unroll
        for (int c = 0; c < 4; ++c) unpack2(acc2[r][c], av[2 * c], av[2 * c + 1]);
        float4* dst = reinterpret_cast<float4*>(&g_acc[js][row * FOUT_ + f0]);
        dst[0] = make_float4(av[0], av[1], av[2], av[3]);
        dst[1] = make_float4(av[4], av[5], av[6], av[7]);
    }
    if (tf == 0) {
        #pragma unroll
        for (int r = 0; r < 4; ++r)
            g_l[js][nb + i0 + ti * 4 + r] = lacc[r];
    }
}

// ============================================================================
// Kernel 3: combine j-splits, normalize, LayerNorm, ELU.  One warp per row.
// ============================================================================
__global__ __launch_bounds__(256) void k3_ln(const float* __restrict__ gamma,
                                             const float* __restrict__ beta,
                                             float* __restrict__ out) {
    const int t = threadIdx.x;
    const int warp = t >> 5, lane = t & 31;
    const int row = blockIdx.x * 8 + warp;
    const size_t base = (size_t)row * FOUT_;

    const float v0 = g_acc[0][base + lane]      + g_acc[1][base + lane];
    const float v1 = g_acc[0][base + 32 + lane] + g_acc[1][base + 32 + lane];
    const float l  = g_l[0][row] + g_l[1][row];
    const float inv = 1.f / l;
    const float h0 = v0 * inv, h1 = v1 * inv;

    float s = h0 + h1;
    #pragma unroll
    for (int o = 16; o; o >>= 1) s += __shfl_xor_sync(0xffffffffu, s, o);
    const float mu = s * (1.f / 64.f);

    const float d0 = h0 - mu, d1 = h1 - mu;
    float vs = d0 * d0 + d1 * d1;
    #pragma unroll
    for (int o = 16; o; o >>= 1) vs += __shfl_xor_sync(0xffffffffu, vs, o);
    const float rstd = rsqrtf(vs * (1.f / 64.f) + 1e-5f);

    const float y0 = d0 * rstd * gamma[lane]      + beta[lane];
    const float y1 = d1 * rstd * gamma[lane + 32] + beta[lane + 32];
    out[base + lane]      = (y0 > 0.f) ? y0 : expm1f(y0);
    out[base + 32 + lane] = (y1 > 0.f) ? y1 : expm1f(y1);
}

// ============================================================================
extern "C" void kernel_launch(void* const* d_in, const int* in_sizes, int n_in,
                              void* d_out, int out_size) {
    const float* x     = (const float*)d_in[0];
    const int*   adj   = (const int*)  d_in[1];
    const float* W     = (const float*)d_in[2];
    const float* a     = (const float*)d_in[3];
    const float* gamma = (const float*)d_in[4];
    const float* beta  = (const float*)d_in[5];
    float* out = (float*)d_out;

    const int smem2 = (4096 + 8192 + 3 * 128 + 3 * 64) * (int)sizeof(float); // 51456 B
    cudaFuncSetAttribute(k2_attn, cudaFuncAttributeMaxDynamicSharedMemorySize, smem2);

    k1_proj<<<BN_ / 64, 128>>>(x, W, a);
    k2_attn<<<dim3(N_ / TI, B_, JSPLIT), 256, smem2>>>(adj);
    k3_ln<<<BN_ / 8, 256>>>(gamma, beta, out);
}

// round 5
// speedup vs baseline: 1.5824x; 1.5816x over previous
#include <cuda_runtime.h>
#include <math.h>

#define B_    8
#define N_    2048
#define FIN_  128
#define FOUT_ 64
#define BN_   (B_ * N_)

#define TI      128
#define TJ      64
#define JSPLIT  2
#define JCHUNK  (N_ / JSPLIT)

// smem float offsets for k2
#define HP      72            // H tile pitch (64 data + col64=1.0 + zeros)
#define PP      68            // P tile pitch
#define OFF_H   0
#define OFF_P   (TJ * HP)                  // 4608
#define OFF_S1  (OFF_P + TI * PP)          // 13312
#define OFF_E1  (OFF_S1 + 128)
#define OFF_F1  (OFF_E1 + 128)
#define OFF_S2  (OFF_F1 + 128)
#define OFF_E2  (OFF_S2 + 64)
#define OFF_F2  (OFF_E2 + 64)
#define SM2_FLOATS (OFF_F2 + 64)           // 13888 floats = 55552 B

// k1 smem
#define XPITCH  129
#define K1_OFF_W  0
#define K1_OFF_X  (FIN_ * FOUT_)               // 8192
#define K1_OFF_R1 (K1_OFF_X + 64 * XPITCH)     // 8192 + 8256
#define K1_OFF_R2 (K1_OFF_R1 + 256)
#define SM1_FLOATS (K1_OFF_R2 + 256)           // 16960 floats = 67840 B

__device__ __forceinline__ unsigned tf32_of(float f) {
    unsigned r;
    asm("cvt.rna.tf32.f32 %0, %1;" : "=r"(r) : "f"(f));
    return r;
}
__device__ __forceinline__ void mma_tf32(float& c0, float& c1, float& c2, float& c3,
                                         unsigned a0, unsigned a1, unsigned a2, unsigned a3,
                                         unsigned b0, unsigned b1) {
    asm("mma.sync.aligned.m16n8k8.row.col.f32.tf32.tf32.f32 "
        "{%0,%1,%2,%3}, {%4,%5,%6,%7}, {%8,%9}, {%0,%1,%2,%3};"
        : "+f"(c0), "+f"(c1), "+f"(c2), "+f"(c3)
        : "r"(a0), "r"(a1), "r"(a2), "r"(a3), "r"(b0), "r"(b1));
}

// -------- scratch --------
__device__ float g_h[BN_ * FOUT_];
__device__ float g_s1[BN_], g_s2[BN_];
__device__ float g_E1[BN_], g_F1[BN_], g_E2[BN_], g_F2[BN_];
__device__ float g_acc[JSPLIT][BN_ * FOUT_];
__device__ float g_l[JSPLIT][BN_];

// ============================================================================
// Kernel 1: h = x @ W + s1/s2 dots + per-node exps.  x staged via smem
// (pitch 129 -> conflict-free), W broadcast from smem (warp-uniform).
// 256 blocks x 128 threads, 64 rows/block, 2 rows/thread.
// ============================================================================
__global__ __launch_bounds__(128) void k1_proj(const float* __restrict__ x,
                                               const float* __restrict__ W,
                                               const float* __restrict__ a) {
    extern __shared__ float sm1[];
    float* sW  = sm1 + K1_OFF_W;
    float* sx  = sm1 + K1_OFF_X;
    float* sr1 = sm1 + K1_OFF_R1;
    float* sr2 = sm1 + K1_OFF_R2;

    const int t = threadIdx.x;
    const int rowbase = blockIdx.x * 64;

    {   // W -> smem (pitch 64, reads are warp-uniform => broadcast)
        float4*       d = reinterpret_cast<float4*>(sW);
        const float4* s = reinterpret_cast<const float4*>(W);
        #pragma unroll
        for (int q = 0; q < 16; ++q) d[t + q * 128] = s[t + q * 128];
    }
    {   // x rows -> smem pitch 129 (coalesced global reads)
        const float4* s = reinterpret_cast<const float4*>(x);
        #pragma unroll
        for (int q = 0; q < 16; ++q) {
            const int idx = t + q * 128;       // 0..2047
            const int row = idx >> 5;          // 0..63
            const int k4  = idx & 31;
            float4 v = s[(size_t)(rowbase + row) * 32 + k4];
            float* dst = &sx[row * XPITCH + k4 * 4];
            dst[0] = v.x; dst[1] = v.y; dst[2] = v.z; dst[3] = v.w;
        }
    }
    __syncthreads();

    const int fg = t >> 5;       // 0..3 : 16-col group of FOUT
    const int rt = t & 31;

    float acc[2][16];
    #pragma unroll
    for (int r = 0; r < 2; ++r)
        #pragma unroll
        for (int c = 0; c < 16; ++c) acc[r][c] = 0.f;

    for (int k4 = 0; k4 < FIN_ / 4; ++k4) {
        float xs[2][4];
        #pragma unroll
        for (int rr = 0; rr < 2; ++rr) {
            const float* xr = &sx[(rt + 32 * rr) * XPITCH + k4 * 4];
            xs[rr][0] = xr[0]; xs[rr][1] = xr[1]; xs[rr][2] = xr[2]; xs[rr][3] = xr[3];
        }
        #pragma unroll
        for (int q = 0; q < 4; ++q) {
            const int k = k4 * 4 + q;
            const float4* wr = reinterpret_cast<const float4*>(&sW[k * FOUT_ + fg * 16]);
            const float4 w0 = wr[0], w1 = wr[1], w2 = wr[2], w3 = wr[3];
            #pragma unroll
            for (int rr = 0; rr < 2; ++rr) {
                const float xv = xs[rr][q];
                acc[rr][0]  += xv * w0.x; acc[rr][1]  += xv * w0.y;
                acc[rr][2]  += xv * w0.z; acc[rr][3]  += xv * w0.w;
                acc[rr][4]  += xv * w1.x; acc[rr][5]  += xv * w1.y;
                acc[rr][6]  += xv * w1.z; acc[rr][7]  += xv * w1.w;
                acc[rr][8]  += xv * w2.x; acc[rr][9]  += xv * w2.y;
                acc[rr][10] += xv * w2.z; acc[rr][11] += xv * w2.w;
                acc[rr][12] += xv * w3.x; acc[rr][13] += xv * w3.y;
                acc[rr][14] += xv * w3.z; acc[rr][15] += xv * w3.w;
            }
        }
    }

    float a1v[16], a2v[16];
    #pragma unroll
    for (int f = 0; f < 16; ++f) {
        a1v[f] = a[fg * 16 + f];
        a2v[f] = a[FOUT_ + fg * 16 + f];
    }
    #pragma unroll
    for (int rr = 0; rr < 2; ++rr) {
        const int rloc = rt + 32 * rr;
        const size_t row = (size_t)rowbase + rloc;
        float4* hd = reinterpret_cast<float4*>(&g_h[row * FOUT_ + fg * 16]);
        #pragma unroll
        for (int f4 = 0; f4 < 4; ++f4)
            hd[f4] = make_float4(acc[rr][f4 * 4], acc[rr][f4 * 4 + 1],
                                 acc[rr][f4 * 4 + 2], acc[rr][f4 * 4 + 3]);
        float ps1 = 0.f, ps2 = 0.f;
        #pragma unroll
        for (int f = 0; f < 16; ++f) {
            ps1 += acc[rr][f] * a1v[f];
            ps2 += acc[rr][f] * a2v[f];
        }
        sr1[rloc * 4 + fg] = ps1;
        sr2[rloc * 4 + fg] = ps2;
    }
    __syncthreads();
    if (t < 64) {
        const int row = rowbase + t;
        const float s1 = sr1[t * 4] + sr1[t * 4 + 1] + sr1[t * 4 + 2] + sr1[t * 4 + 3];
        const float s2 = sr2[t * 4] + sr2[t * 4 + 1] + sr2[t * 4 + 2] + sr2[t * 4 + 3];
        g_s1[row] = s1;
        g_s2[row] = s2;
        g_E1[row] = expf(s1);
        g_F1[row] = expf(0.2f * s1);
        g_E2[row] = expf(s2);
        g_F2[row] = expf(0.2f * s2);
    }
}

// ============================================================================
// Kernel 2: fused masked attention + aggregation via tf32 tensor-core MMA.
// Phase A: P tile (fp32, exact, no per-pair MUFU) into smem [i][j] pitch 68.
// Phase B: m16n8k8 tf32 mma; H tile [j][f] pitch 72 with col64=1.0 so the
//          9th n-group accumulates the softmax denominator l for free.
// 256 threads = 8 warps; warp w owns i-rows [w*16, w*16+16) x all 64 f.
// ============================================================================
__global__ __launch_bounds__(256) void k2_attn(const int* __restrict__ adj) {
    extern __shared__ float sm[];
    float* smH  = sm + OFF_H;
    float* smP  = sm + OFF_P;
    float* s_s1 = sm + OFF_S1;
    float* s_E1 = sm + OFF_E1;
    float* s_F1 = sm + OFF_F1;
    float* s_s2 = sm + OFF_S2;
    float* s_E2 = sm + OFF_E2;
    float* s_F2 = sm + OFF_F2;

    const int t  = threadIdx.x;
    const int b  = blockIdx.y;
    const int i0 = blockIdx.x * TI;
    const int js = blockIdx.z;
    const int jbase = js * JCHUNK;
    const int nb = b * N_;

    if (t < TI) {
        const int g = nb + i0 + t;
        s_s1[t] = g_s1[g]; s_E1[t] = g_E1[g]; s_F1[t] = g_F1[g];
    }

    const int w    = t >> 5;          // warp id 0..7 -> i-group
    const int lane = t & 31;
    const int grp  = lane >> 2;       // 0..7
    const int tig  = lane & 3;        // 0..3

    float acc[9][4];                  // 8 f-groups + 1 "ones" group (l)
    #pragma unroll
    for (int n = 0; n < 9; ++n)
        #pragma unroll
        for (int c = 0; c < 4; ++c) acc[n][c] = 0.f;

    const int j4  = t & 15;           // phase-A j quad
    const int ibA = t >> 4;           // phase-A i base

    for (int jt = 0; jt < JCHUNK; jt += TJ) {
        const int j0 = jbase + jt;
        __syncthreads();
        {   // load H tile [TJ][HP]: cols 0..63 = g_h, col 64 = 1.0, 65..71 = 0
            const float4* src = reinterpret_cast<const float4*>(&g_h[(size_t)(nb + j0) * FOUT_]);
            for (int idx = t; idx < TJ * (HP / 4); idx += 256) {
                const int row = idx / (HP / 4);       // HP/4 = 18
                const int c4  = idx % (HP / 4);
                float4 v;
                if (c4 < 16)      v = src[row * 16 + c4];
                else if (c4 == 16) v = make_float4(1.f, 0.f, 0.f, 0.f);
                else               v = make_float4(0.f, 0.f, 0.f, 0.f);
                float* dst = &smH[row * HP + c4 * 4];
                dst[0] = v.x; dst[1] = v.y; dst[2] = v.z; dst[3] = v.w;
            }
        }
        if (t < 64)        s_s2[t]       = g_s2[nb + j0 + t];
        else if (t < 128)  s_E2[t - 64]  = g_E2[nb + j0 + t - 64];
        else if (t < 192)  s_F2[t - 128] = g_F2[nb + j0 + t - 128];
        __syncthreads();

        // ---- Phase A: P tile into smP[i*PP + j] ----
        #pragma unroll
        for (int ii = 0; ii < 8; ++ii) {
            const int i = ibA + ii * 16;
            const float s1 = s_s1[i], E1 = s_E1[i], F1 = s_F1[i];
            const int4 aj = *reinterpret_cast<const int4*>(
                adj + (size_t)(nb + i0 + i) * N_ + j0 + j4 * 4);
            const int av[4] = {aj.x, aj.y, aj.z, aj.w};
            float p[4];
            #pragma unroll
            for (int q = 0; q < 4; ++q) {
                const int j = j4 * 4 + q;
                const float xsum = s1 + s_s2[j];
                float pv = (xsum > 0.f) ? (E1 * s_E2[j]) : (F1 * s_F2[j]);
                p[q] = (av[q] > 0) ? pv : 0.f;
            }
            float* dst = &smP[i * PP + j4 * 4];
            dst[0] = p[0]; dst[1] = p[1]; dst[2] = p[2]; dst[3] = p[3];
        }
        __syncthreads();

        // ---- Phase B: tf32 MMA, K = TJ in chunks of 8 ----
        #pragma unroll
        for (int k0 = 0; k0 < TJ; k0 += 8) {
            const int ia = w * 16 + grp;
            const unsigned a0 = tf32_of(smP[ ia      * PP + k0 + tig]);
            const unsigned a1 = tf32_of(smP[(ia + 8) * PP + k0 + tig]);
            const unsigned a2 = tf32_of(smP[ ia      * PP + k0 + tig + 4]);
            const unsigned a3 = tf32_of(smP[(ia + 8) * PP + k0 + tig + 4]);
            #pragma unroll
            for (int ng = 0; ng < 9; ++ng) {
                const int f = ng * 8 + grp;
                const unsigned b0 = tf32_of(smH[(k0 + tig)     * HP + f]);
                const unsigned b1 = tf32_of(smH[(k0 + tig + 4) * HP + f]);
                mma_tf32(acc[ng][0], acc[ng][1], acc[ng][2], acc[ng][3],
                         a0, a1, a2, a3, b0, b1);
            }
        }
    }

    // write partials: warp w rows r0 = i0 + w*16 + grp, r1 = r0 + 8
    const size_t r0 = (size_t)nb + i0 + w * 16 + grp;
    const size_t r1 = r0 + 8;
    #pragma unroll
    for (int ng = 0; ng < 8; ++ng) {
        const int f = ng * 8 + tig * 2;
        float2* d0 = reinterpret_cast<float2*>(&g_acc[js][r0 * FOUT_ + f]);
        float2* d1 = reinterpret_cast<float2*>(&g_acc[js][r1 * FOUT_ + f]);
        *d0 = make_float2(acc[ng][0], acc[ng][1]);
        *d1 = make_float2(acc[ng][2], acc[ng][3]);
    }
    if (tig == 0) {   // ones-column: col 64 holds l
        g_l[js][r0] = acc[8][0];
        g_l[js][r1] = acc[8][2];
    }
}

// ============================================================================
// Kernel 3: combine j-splits, normalize, LayerNorm, ELU.  One warp per row.
// ============================================================================
__global__ __launch_bounds__(256) void k3_ln(const float* __restrict__ gamma,
                                             const float* __restrict__ beta,
                                             float* __restrict__ out) {
    const int t = threadIdx.x;
    const int warp = t >> 5, lane = t & 31;
    const int row = blockIdx.x * 8 + warp;
    const size_t base = (size_t)row * FOUT_;

    const float v0 = g_acc[0][base + lane]      + g_acc[1][base + lane];
    const float v1 = g_acc[0][base + 32 + lane] + g_acc[1][base + 32 + lane];
    const float l  = g_l[0][row] + g_l[1][row];
    const float inv = 1.f / l;
    const float h0 = v0 * inv, h1 = v1 * inv;

    float s = h0 + h1;
    #pragma unroll
    for (int o = 16; o; o >>= 1) s += __shfl_xor_sync(0xffffffffu, s, o);
    const float mu = s * (1.f / 64.f);

    const float d0 = h0 - mu, d1 = h1 - mu;
    float vs = d0 * d0 + d1 * d1;
    #pragma unroll
    for (int o = 16; o; o >>= 1) vs += __shfl_xor_sync(0xffffffffu, vs, o);
    const float rstd = rsqrtf(vs * (1.f / 64.f) + 1e-5f);

    const float y0 = d0 * rstd * gamma[lane]      + beta[lane];
    const float y1 = d1 * rstd * gamma[lane + 32] + beta[lane + 32];
    out[base + lane]      = (y0 > 0.f) ? y0 : expm1f(y0);
    out[base + 32 + lane] = (y1 > 0.f) ? y1 : expm1f(y1);
}

// ============================================================================
extern "C" void kernel_launch(void* const* d_in, const int* in_sizes, int n_in,
                              void* d_out, int out_size) {
    const float* x     = (const float*)d_in[0];
    const int*   adj   = (const int*)  d_in[1];
    const float* W     = (const float*)d_in[2];
    const float* a     = (const float*)d_in[3];
    const float* gamma = (const float*)d_in[4];
    const float* beta  = (const float*)d_in[5];
    float* out = (float*)d_out;

    const int smem1 = SM1_FLOATS * (int)sizeof(float);   // 67840 B
    const int smem2 = SM2_FLOATS * (int)sizeof(float);   // 55552 B
    cudaFuncSetAttribute(k1_proj, cudaFuncAttributeMaxDynamicSharedMemorySize, smem1);
    cudaFuncSetAttribute(k2_attn, cudaFuncAttributeMaxDynamicSharedMemorySize, smem2);

    k1_proj<<<BN_ / 64, 128, smem1>>>(x, W, a);
    k2_attn<<<dim3(N_ / TI, B_, JSPLIT), 256, smem2>>>(adj);
    k3_ln<<<BN_ / 8, 256>>>(gamma, beta, out);
}

// round 6
// speedup vs baseline: 1.6667x; 1.0533x over previous
#include <cuda_runtime.h>
#include <math.h>

#define B_    8
#define N_    2048
#define FIN_  128
#define FOUT_ 64
#define BN_   (B_ * N_)

#define TI      128
#define TJ      64
#define JSPLIT  2
#define JCHUNK  (N_ / JSPLIT)

// smem float offsets for k2
#define HP      72            // H tile pitch (64 data + col64=1.0 + zeros)
#define PP      68            // P tile pitch
#define OFF_H   0
#define OFF_P   (TJ * HP)                  // 4608
#define OFF_S1  (OFF_P + TI * PP)          // 13312
#define OFF_E1  (OFF_S1 + 128)
#define OFF_F1  (OFF_E1 + 128)
#define OFF_S2  (OFF_F1 + 128)
#define OFF_E2  (OFF_S2 + 64)
#define OFF_F2  (OFF_E2 + 64)
#define SM2_FLOATS (OFF_F2 + 64)           // 13888 floats = 55552 B

// k1 smem
#define XPITCH  129
#define K1_OFF_W  0
#define K1_OFF_X  (FIN_ * FOUT_)               // 8192
#define K1_OFF_R1 (K1_OFF_X + 64 * XPITCH)
#define K1_OFF_R2 (K1_OFF_R1 + 256)
#define SM1_FLOATS (K1_OFF_R2 + 256)           // 16960 floats = 67840 B

__device__ __forceinline__ unsigned tf32_of(float f) {
    unsigned r;
    asm("cvt.rna.tf32.f32 %0, %1;" : "=r"(r) : "f"(f));
    return r;
}
__device__ __forceinline__ void mma_tf32(float& c0, float& c1, float& c2, float& c3,
                                         unsigned a0, unsigned a1, unsigned a2, unsigned a3,
                                         unsigned b0, unsigned b1) {
    asm("mma.sync.aligned.m16n8k8.row.col.f32.tf32.tf32.f32 "
        "{%0,%1,%2,%3}, {%4,%5,%6,%7}, {%8,%9}, {%0,%1,%2,%3};"
        : "+f"(c0), "+f"(c1), "+f"(c2), "+f"(c3)
        : "r"(a0), "r"(a1), "r"(a2), "r"(a3), "r"(b0), "r"(b1));
}

// -------- scratch --------
__device__ float g_h[BN_ * FOUT_];
__device__ float g_s1[BN_], g_s2[BN_];
__device__ float g_E1[BN_], g_F1[BN_], g_E2[BN_], g_F2[BN_];
__device__ float g_acc[JSPLIT][BN_ * FOUT_];
__device__ float g_l[JSPLIT][BN_];

// ============================================================================
// Kernel 1: h = x @ W + s1/s2 dots + per-node exps. (unchanged from R5)
// ============================================================================
__global__ __launch_bounds__(128) void k1_proj(const float* __restrict__ x,
                                               const float* __restrict__ W,
                                               const float* __restrict__ a) {
    extern __shared__ float sm1[];
    float* sW  = sm1 + K1_OFF_W;
    float* sx  = sm1 + K1_OFF_X;
    float* sr1 = sm1 + K1_OFF_R1;
    float* sr2 = sm1 + K1_OFF_R2;

    const int t = threadIdx.x;
    const int rowbase = blockIdx.x * 64;

    {
        float4*       d = reinterpret_cast<float4*>(sW);
        const float4* s = reinterpret_cast<const float4*>(W);
        #pragma unroll
        for (int q = 0; q < 16; ++q) d[t + q * 128] = s[t + q * 128];
    }
    {
        const float4* s = reinterpret_cast<const float4*>(x);
        #pragma unroll
        for (int q = 0; q < 16; ++q) {
            const int idx = t + q * 128;
            const int row = idx >> 5;
            const int k4  = idx & 31;
            float4 v = s[(size_t)(rowbase + row) * 32 + k4];
            float* dst = &sx[row * XPITCH + k4 * 4];
            dst[0] = v.x; dst[1] = v.y; dst[2] = v.z; dst[3] = v.w;
        }
    }
    __syncthreads();

    const int fg = t >> 5;
    const int rt = t & 31;

    float acc[2][16];
    #pragma unroll
    for (int r = 0; r < 2; ++r)
        #pragma unroll
        for (int c = 0; c < 16; ++c) acc[r][c] = 0.f;

    for (int k4 = 0; k4 < FIN_ / 4; ++k4) {
        float xs[2][4];
        #pragma unroll
        for (int rr = 0; rr < 2; ++rr) {
            const float* xr = &sx[(rt + 32 * rr) * XPITCH + k4 * 4];
            xs[rr][0] = xr[0]; xs[rr][1] = xr[1]; xs[rr][2] = xr[2]; xs[rr][3] = xr[3];
        }
        #pragma unroll
        for (int q = 0; q < 4; ++q) {
            const int k = k4 * 4 + q;
            const float4* wr = reinterpret_cast<const float4*>(&sW[k * FOUT_ + fg * 16]);
            const float4 w0 = wr[0], w1 = wr[1], w2 = wr[2], w3 = wr[3];
            #pragma unroll
            for (int rr = 0; rr < 2; ++rr) {
                const float xv = xs[rr][q];
                acc[rr][0]  += xv * w0.x; acc[rr][1]  += xv * w0.y;
                acc[rr][2]  += xv * w0.z; acc[rr][3]  += xv * w0.w;
                acc[rr][4]  += xv * w1.x; acc[rr][5]  += xv * w1.y;
                acc[rr][6]  += xv * w1.z; acc[rr][7]  += xv * w1.w;
                acc[rr][8]  += xv * w2.x; acc[rr][9]  += xv * w2.y;
                acc[rr][10] += xv * w2.z; acc[rr][11] += xv * w2.w;
                acc[rr][12] += xv * w3.x; acc[rr][13] += xv * w3.y;
                acc[rr][14] += xv * w3.z; acc[rr][15] += xv * w3.w;
            }
        }
    }

    float a1v[16], a2v[16];
    #pragma unroll
    for (int f = 0; f < 16; ++f) {
        a1v[f] = a[fg * 16 + f];
        a2v[f] = a[FOUT_ + fg * 16 + f];
    }
    #pragma unroll
    for (int rr = 0; rr < 2; ++rr) {
        const int rloc = rt + 32 * rr;
        const size_t row = (size_t)rowbase + rloc;
        float4* hd = reinterpret_cast<float4*>(&g_h[row * FOUT_ + fg * 16]);
        #pragma unroll
        for (int f4 = 0; f4 < 4; ++f4)
            hd[f4] = make_float4(acc[rr][f4 * 4], acc[rr][f4 * 4 + 1],
                                 acc[rr][f4 * 4 + 2], acc[rr][f4 * 4 + 3]);
        float ps1 = 0.f, ps2 = 0.f;
        #pragma unroll
        for (int f = 0; f < 16; ++f) {
            ps1 += acc[rr][f] * a1v[f];
            ps2 += acc[rr][f] * a2v[f];
        }
        sr1[rloc * 4 + fg] = ps1;
        sr2[rloc * 4 + fg] = ps2;
    }
    __syncthreads();
    if (t < 64) {
        const int row = rowbase + t;
        const float s1 = sr1[t * 4] + sr1[t * 4 + 1] + sr1[t * 4 + 2] + sr1[t * 4 + 3];
        const float s2 = sr2[t * 4] + sr2[t * 4 + 1] + sr2[t * 4 + 2] + sr2[t * 4 + 3];
        g_s1[row] = s1;
        g_s2[row] = s2;
        g_E1[row] = expf(s1);
        g_F1[row] = expf(0.2f * s1);
        g_E2[row] = expf(s2);
        g_F2[row] = expf(0.2f * s2);
    }
}

// ============================================================================
// Kernel 2: fused masked attention + aggregation via tf32 MMA.
// R6: smP/smH hold PRE-CONVERTED tf32 bit patterns (no cvt in phase B),
//     and adj is register-double-buffered (DRAM latency hidden under MMA).
// ============================================================================
__global__ __launch_bounds__(256) void k2_attn(const int* __restrict__ adj) {
    extern __shared__ float sm[];
    float* smH  = sm + OFF_H;
    float* smP  = sm + OFF_P;
    float* s_s1 = sm + OFF_S1;
    float* s_E1 = sm + OFF_E1;
    float* s_F1 = sm + OFF_F1;
    float* s_s2 = sm + OFF_S2;
    float* s_E2 = sm + OFF_E2;
    float* s_F2 = sm + OFF_F2;

    const int t  = threadIdx.x;
    const int b  = blockIdx.y;
    const int i0 = blockIdx.x * TI;
    const int js = blockIdx.z;
    const int jbase = js * JCHUNK;
    const int nb = b * N_;

    if (t < TI) {
        const int g = nb + i0 + t;
        s_s1[t] = g_s1[g]; s_E1[t] = g_E1[g]; s_F1[t] = g_F1[g];
    }

    const int w    = t >> 5;
    const int lane = t & 31;
    const int grp  = lane >> 2;
    const int tig  = lane & 3;

    float acc[9][4];
    #pragma unroll
    for (int n = 0; n < 9; ++n)
        #pragma unroll
        for (int c = 0; c < 4; ++c) acc[n][c] = 0.f;

    const int j4  = t & 15;
    const int ibA = t >> 4;

    // prefetch adj for the first tile
    int4 adjreg[8];
    #pragma unroll
    for (int ii = 0; ii < 8; ++ii) {
        const int i = ibA + ii * 16;
        adjreg[ii] = *reinterpret_cast<const int4*>(
            adj + (size_t)(nb + i0 + i) * N_ + jbase + j4 * 4);
    }

    const unsigned one_tf = tf32_of(1.f);

    for (int jt = 0; jt < JCHUNK; jt += TJ) {
        const int j0 = jbase + jt;
        __syncthreads();
        {   // load H tile [TJ][HP] as tf32 bits: cols 0..63 = tf32(g_h), 64 = tf32(1), 65..71 = 0
            const float4* src = reinterpret_cast<const float4*>(&g_h[(size_t)(nb + j0) * FOUT_]);
            for (int idx = t; idx < TJ * (HP / 4); idx += 256) {
                const int row = idx / (HP / 4);
                const int c4  = idx % (HP / 4);
                unsigned o0, o1, o2, o3;
                if (c4 < 16) {
                    float4 v = src[row * 16 + c4];
                    o0 = tf32_of(v.x); o1 = tf32_of(v.y);
                    o2 = tf32_of(v.z); o3 = tf32_of(v.w);
                } else if (c4 == 16) {
                    o0 = one_tf; o1 = 0u; o2 = 0u; o3 = 0u;
                } else {
                    o0 = o1 = o2 = o3 = 0u;
                }
                float* dst = &smH[row * HP + c4 * 4];
                dst[0] = __uint_as_float(o0); dst[1] = __uint_as_float(o1);
                dst[2] = __uint_as_float(o2); dst[3] = __uint_as_float(o3);
            }
        }
        if (t < 64)        s_s2[t]       = g_s2[nb + j0 + t];
        else if (t < 128)  s_E2[t - 64]  = g_E2[nb + j0 + t - 64];
        else if (t < 192)  s_F2[t - 128] = g_F2[nb + j0 + t - 128];
        __syncthreads();

        // ---- Phase A: P tile (tf32 bits) into smP[i*PP + j] ----
        #pragma unroll
        for (int ii = 0; ii < 8; ++ii) {
            const int i = ibA + ii * 16;
            const float s1 = s_s1[i], E1 = s_E1[i], F1 = s_F1[i];
            const int av[4] = {adjreg[ii].x, adjreg[ii].y, adjreg[ii].z, adjreg[ii].w};
            float* dst = &smP[i * PP + j4 * 4];
            #pragma unroll
            for (int q = 0; q < 4; ++q) {
                const int j = j4 * 4 + q;
                const float xsum = s1 + s_s2[j];
                float pv = (xsum > 0.f) ? (E1 * s_E2[j]) : (F1 * s_F2[j]);
                pv = (av[q] > 0) ? pv : 0.f;
                dst[q] = __uint_as_float(tf32_of(pv));
            }
        }

        // prefetch adj for the next tile (hidden under phase B's MMA wall)
        if (jt + TJ < JCHUNK) {
            const int jn = j0 + TJ + j4 * 4;
            #pragma unroll
            for (int ii = 0; ii < 8; ++ii) {
                const int i = ibA + ii * 16;
                adjreg[ii] = *reinterpret_cast<const int4*>(
                    adj + (size_t)(nb + i0 + i) * N_ + jn);
            }
        }
        __syncthreads();

        // ---- Phase B: tf32 MMA, no conversions ----
        #pragma unroll
        for (int k0 = 0; k0 < TJ; k0 += 8) {
            const int ia = w * 16 + grp;
            const unsigned a0 = __float_as_uint(smP[ ia      * PP + k0 + tig]);
            const unsigned a1 = __float_as_uint(smP[(ia + 8) * PP + k0 + tig]);
            const unsigned a2 = __float_as_uint(smP[ ia      * PP + k0 + tig + 4]);
            const unsigned a3 = __float_as_uint(smP[(ia + 8) * PP + k0 + tig + 4]);
            #pragma unroll
            for (int ng = 0; ng < 9; ++ng) {
                const int f = ng * 8 + grp;
                const unsigned b0 = __float_as_uint(smH[(k0 + tig)     * HP + f]);
                const unsigned b1 = __float_as_uint(smH[(k0 + tig + 4) * HP + f]);
                mma_tf32(acc[ng][0], acc[ng][1], acc[ng][2], acc[ng][3],
                         a0, a1, a2, a3, b0, b1);
            }
        }
    }

    // write partials
    const size_t r0 = (size_t)nb + i0 + w * 16 + grp;
    const size_t r1 = r0 + 8;
    #pragma unroll
    for (int ng = 0; ng < 8; ++ng) {
        const int f = ng * 8 + tig * 2;
        float2* d0 = reinterpret_cast<float2*>(&g_acc[js][r0 * FOUT_ + f]);
        float2* d1 = reinterpret_cast<float2*>(&g_acc[js][r1 * FOUT_ + f]);
        *d0 = make_float2(acc[ng][0], acc[ng][1]);
        *d1 = make_float2(acc[ng][2], acc[ng][3]);
    }
    if (tig == 0) {
        g_l[js][r0] = acc[8][0];
        g_l[js][r1] = acc[8][2];
    }
}

// ============================================================================
// Kernel 3: combine j-splits, normalize, LayerNorm, ELU. (unchanged)
// ============================================================================
__global__ __launch_bounds__(256) void k3_ln(const float* __restrict__ gamma,
                                             const float* __restrict__ beta,
                                             float* __restrict__ out) {
    const int t = threadIdx.x;
    const int warp = t >> 5, lane = t & 31;
    const int row = blockIdx.x * 8 + warp;
    const size_t base = (size_t)row * FOUT_;

    const float v0 = g_acc[0][base + lane]      + g_acc[1][base + lane];
    const float v1 = g_acc[0][base + 32 + lane] + g_acc[1][base + 32 + lane];
    const float l  = g_l[0][row] + g_l[1][row];
    const float inv = 1.f / l;
    const float h0 = v0 * inv, h1 = v1 * inv;

    float s = h0 + h1;
    #pragma unroll
    for (int o = 16; o; o >>= 1) s += __shfl_xor_sync(0xffffffffu, s, o);
    const float mu = s * (1.f / 64.f);

    const float d0 = h0 - mu, d1 = h1 - mu;
    float vs = d0 * d0 + d1 * d1;
    #pragma unroll
    for (int o = 16; o; o >>= 1) vs += __shfl_xor_sync(0xffffffffu, vs, o);
    const float rstd = rsqrtf(vs * (1.f / 64.f) + 1e-5f);

    const float y0 = d0 * rstd * gamma[lane]      + beta[lane];
    const float y1 = d1 * rstd * gamma[lane + 32] + beta[lane + 32];
    out[base + lane]      = (y0 > 0.f) ? y0 : expm1f(y0);
    out[base + 32 + lane] = (y1 > 0.f) ? y1 : expm1f(y1);
}

// ============================================================================
extern "C" void kernel_launch(void* const* d_in, const int* in_sizes, int n_in,
                              void* d_out, int out_size) {
    const float* x     = (const float*)d_in[0];
    const int*   adj   = (const int*)  d_in[1];
    const float* W     = (const float*)d_in[2];
    const float* a     = (const float*)d_in[3];
    const float* gamma = (const float*)d_in[4];
    const float* beta  = (const float*)d_in[5];
    float* out = (float*)d_out;

    const int smem1 = SM1_FLOATS * (int)sizeof(float);   // 67840 B
    const int smem2 = SM2_FLOATS * (int)sizeof(float);   // 55552 B
    cudaFuncSetAttribute(k1_proj, cudaFuncAttributeMaxDynamicSharedMemorySize, smem1);
    cudaFuncSetAttribute(k2_attn, cudaFuncAttributeMaxDynamicSharedMemorySize, smem2);

    k1_proj<<<BN_ / 64, 128, smem1>>>(x, W, a);
    k2_attn<<<dim3(N_ / TI, B_, JSPLIT), 256, smem2>>>(adj);
    k3_ln<<<BN_ / 8, 256>>>(gamma, beta, out);
}

// round 7
// speedup vs baseline: 2.0720x; 1.2432x over previous
#include <cuda_runtime.h>
#include <math.h>

#define B_    8
#define N_    2048
#define FIN_  128
#define FOUT_ 64
#define BN_   (B_ * N_)

#define TI      128
#define TJ      64
#define JSPLIT  2
#define JCHUNK  (N_ / JSPLIT)
#define NT_     (JCHUNK / TJ)          // 16 tiles per block

// k2 smem layout (floats)
#define HP      72                     // H tile pitch (64 data + col64=1.0 + 0s)
#define PP      68                     // P tile pitch
#define HBUF    (TJ * HP)              // 4608
#define PBUF    (TI * PP)              // 8704
#define OFF_P   (2 * HBUF)
#define OFF_S1  (OFF_P + 2 * PBUF)     // 26624
#define OFF_E1  (OFF_S1 + 128)
#define OFF_F1  (OFF_E1 + 128)
#define SM2_FLOATS (OFF_F1 + 128)      // 27008 floats = 108032 B

// k1 smem (32 rows/block)
#define K1ROWS   32
#define XPITCH   129
#define K1_OFF_X (FIN_ * FOUT_)                    // 8192
#define K1_OFF_R1 (K1_OFF_X + K1ROWS * XPITCH)     // 8192 + 4128
#define K1_OFF_R2 (K1_OFF_R1 + 128)
#define SM1_FLOATS (K1_OFF_R2 + 128)               // 12576 floats = 50304 B

__device__ __forceinline__ void mma_tf32(float& c0, float& c1, float& c2, float& c3,
                                         unsigned a0, unsigned a1, unsigned a2, unsigned a3,
                                         unsigned b0, unsigned b1) {
    asm("mma.sync.aligned.m16n8k8.row.col.f32.tf32.tf32.f32 "
        "{%0,%1,%2,%3}, {%4,%5,%6,%7}, {%8,%9}, {%0,%1,%2,%3};"
        : "+f"(c0), "+f"(c1), "+f"(c2), "+f"(c3)
        : "r"(a0), "r"(a1), "r"(a2), "r"(a3), "r"(b0), "r"(b1));
}
__device__ __forceinline__ unsigned smaddr(const void* p) {
    return (unsigned)__cvta_generic_to_shared(p);
}
__device__ __forceinline__ void cpa16(unsigned s, const void* g) {
    asm volatile("cp.async.ca.shared.global [%0], [%1], 16;" :: "r"(s), "l"(g));
}
__device__ __forceinline__ void cpa_commit() {
    asm volatile("cp.async.commit_group;" ::: "memory");
}
__device__ __forceinline__ void cpa_wait0() {
    asm volatile("cp.async.wait_group 0;" ::: "memory");
}

// -------- scratch --------
__device__ float g_h[BN_ * FOUT_];
__device__ float g_s1[BN_], g_s2[BN_];
__device__ float g_E1[BN_], g_F1[BN_], g_E2[BN_], g_F2[BN_];
__device__ float g_acc[JSPLIT][BN_ * FOUT_];
__device__ float g_l[JSPLIT][BN_];

// ============================================================================
// Kernel 1: h = x @ W + s1/s2 dots + per-node exps.
// 512 blocks x 128 threads, 32 rows/block, 1 row/thread x 16 cols.
// ============================================================================
__global__ __launch_bounds__(128) void k1_proj(const float* __restrict__ x,
                                               const float* __restrict__ W,
                                               const float* __restrict__ a) {
    extern __shared__ float sm1[];
    float* sW  = sm1;
    float* sx  = sm1 + K1_OFF_X;
    float* sr1 = sm1 + K1_OFF_R1;
    float* sr2 = sm1 + K1_OFF_R2;

    const int t = threadIdx.x;
    const int rowbase = blockIdx.x * K1ROWS;

    {   // W -> smem (warp-uniform reads later => broadcast)
        float4*       d = reinterpret_cast<float4*>(sW);
        const float4* s = reinterpret_cast<const float4*>(W);
        #pragma unroll
        for (int q = 0; q < 16; ++q) d[t + q * 128] = s[t + q * 128];
    }
    {   // x rows -> smem pitch 129 (coalesced)
        const float4* s = reinterpret_cast<const float4*>(x);
        #pragma unroll
        for (int q = 0; q < 8; ++q) {
            const int idx = t + q * 128;       // 0..1023
            const int row = idx >> 5;          // 0..31
            const int k4  = idx & 31;
            float4 v = s[(size_t)(rowbase + row) * 32 + k4];
            float* dst = &sx[row * XPITCH + k4 * 4];
            dst[0] = v.x; dst[1] = v.y; dst[2] = v.z; dst[3] = v.w;
        }
    }
    __syncthreads();

    const int fg = t >> 5;       // 0..3 : 16-col group of FOUT
    const int row = t & 31;      // one row per thread

    float acc[16];
    #pragma unroll
    for (int c = 0; c < 16; ++c) acc[c] = 0.f;

    for (int k4 = 0; k4 < FIN_ / 4; ++k4) {
        const float* xr = &sx[row * XPITCH + k4 * 4];
        const float xs[4] = {xr[0], xr[1], xr[2], xr[3]};
        #pragma unroll
        for (int q = 0; q < 4; ++q) {
            const int k = k4 * 4 + q;
            const float4* wr = reinterpret_cast<const float4*>(&sW[k * FOUT_ + fg * 16]);
            const float4 w0 = wr[0], w1 = wr[1], w2 = wr[2], w3 = wr[3];
            const float xv = xs[q];
            acc[0]  += xv * w0.x; acc[1]  += xv * w0.y;
            acc[2]  += xv * w0.z; acc[3]  += xv * w0.w;
            acc[4]  += xv * w1.x; acc[5]  += xv * w1.y;
            acc[6]  += xv * w1.z; acc[7]  += xv * w1.w;
            acc[8]  += xv * w2.x; acc[9]  += xv * w2.y;
            acc[10] += xv * w2.z; acc[11] += xv * w2.w;
            acc[12] += xv * w3.x; acc[13] += xv * w3.y;
            acc[14] += xv * w3.z; acc[15] += xv * w3.w;
        }
    }

    // epilogue
    {
        const size_t grow = (size_t)rowbase + row;
        float4* hd = reinterpret_cast<float4*>(&g_h[grow * FOUT_ + fg * 16]);
        #pragma unroll
        for (int f4 = 0; f4 < 4; ++f4)
            hd[f4] = make_float4(acc[f4 * 4], acc[f4 * 4 + 1],
                                 acc[f4 * 4 + 2], acc[f4 * 4 + 3]);
        float ps1 = 0.f, ps2 = 0.f;
        #pragma unroll
        for (int f = 0; f < 16; ++f) {
            ps1 += acc[f] * a[fg * 16 + f];
            ps2 += acc[f] * a[FOUT_ + fg * 16 + f];
        }
        sr1[row * 4 + fg] = ps1;
        sr2[row * 4 + fg] = ps2;
    }
    __syncthreads();
    if (t < K1ROWS) {
        const int grow = rowbase + t;
        const float s1 = sr1[t * 4] + sr1[t * 4 + 1] + sr1[t * 4 + 2] + sr1[t * 4 + 3];
        const float s2 = sr2[t * 4] + sr2[t * 4 + 1] + sr2[t * 4 + 2] + sr2[t * 4 + 3];
        g_s1[grow] = s1;
        g_s2[grow] = s2;
        g_E1[grow] = expf(s1);
        g_F1[grow] = expf(0.2f * s1);
        g_E2[grow] = expf(s2);
        g_F2[grow] = expf(0.2f * s2);
    }
}

// ============================================================================
// Kernel 2: fused masked attention + aggregation, tf32 MMA, software-pipelined.
// Double-buffered smH/smP; per tile: [cp.async H(t+1) + LDG adj/s2(t+1)]
// -> phase B MMA(t) (hides latency) -> phase A(t+1) -> ONE __syncthreads.
// Raw fp32 operands (HMMA.tf32 truncates low mantissa bits internally).
// ============================================================================
__global__ __launch_bounds__(256, 2) void k2_attn(const int* __restrict__ adj) {
    extern __shared__ float sm[];
    float* smHb = sm;                 // [2][TJ*HP]
    float* smPb = sm + OFF_P;         // [2][TI*PP]
    float* s_s1 = sm + OFF_S1;
    float* s_E1 = sm + OFF_E1;
    float* s_F1 = sm + OFF_F1;

    const int t  = threadIdx.x;
    const int b  = blockIdx.y;
    const int i0 = blockIdx.x * TI;
    const int js = blockIdx.z;
    const int jbase = js * JCHUNK;
    const int nb = b * N_;

    if (t < TI) {
        const int g = nb + i0 + t;
        s_s1[t] = g_s1[g]; s_E1[t] = g_E1[g]; s_F1[t] = g_F1[g];
    }
    {   // ones-column constants for BOTH H buffers: cols 64..71
        const int bufi = t >> 7;          // 0..1
        const int rem  = t & 127;
        const int row  = rem >> 1;        // 0..63
        const int half = rem & 1;
        float4 v = (half == 0) ? make_float4(1.f, 0.f, 0.f, 0.f)
                               : make_float4(0.f, 0.f, 0.f, 0.f);
        *reinterpret_cast<float4*>(&smHb[bufi * HBUF + row * HP + 64 + half * 4]) = v;
    }

    const int w    = t >> 5;
    const int lane = t & 31;
    const int grp  = lane >> 2;
    const int tig  = lane & 3;
    const int j4   = t & 15;
    const int ibA  = t >> 4;

    float acc[9][4];
    #pragma unroll
    for (int n = 0; n < 9; ++n)
        #pragma unroll
        for (int c = 0; c < 4; ++c) acc[n][c] = 0.f;

    int4 adjreg[8];
    float4 s2v, E2v, F2v;

    // ---------------- prologue: produce tile 0 into buffer 0 ----------------
    {
        const int j0 = jbase;
        // async H(0)
        #pragma unroll
        for (int q = 0; q < 4; ++q) {
            const int idx = t + q * 256;
            const int row = idx >> 4, c4 = idx & 15;
            cpa16(smaddr(&smHb[row * HP + c4 * 4]),
                  &g_h[(size_t)(nb + j0 + row) * FOUT_ + c4 * 4]);
        }
        cpa_commit();
        #pragma unroll
        for (int ii = 0; ii < 8; ++ii) {
            const int i = ibA + ii * 16;
            adjreg[ii] = *reinterpret_cast<const int4*>(
                adj + (size_t)(nb + i0 + i) * N_ + j0 + j4 * 4);
        }
        s2v = *reinterpret_cast<const float4*>(&g_s2[nb + j0 + j4 * 4]);
        E2v = *reinterpret_cast<const float4*>(&g_E2[nb + j0 + j4 * 4]);
        F2v = *reinterpret_cast<const float4*>(&g_F2[nb + j0 + j4 * 4]);
        __syncthreads();   // s_s1/E1/F1 + constant cols visible
        // phase A(0) -> smP buf0
        const float s2a[4] = {s2v.x, s2v.y, s2v.z, s2v.w};
        const float E2a[4] = {E2v.x, E2v.y, E2v.z, E2v.w};
        const float F2a[4] = {F2v.x, F2v.y, F2v.z, F2v.w};
        #pragma unroll
        for (int ii = 0; ii < 8; ++ii) {
            const int i = ibA + ii * 16;
            const float s1 = s_s1[i], E1 = s_E1[i], F1 = s_F1[i];
            const int av[4] = {adjreg[ii].x, adjreg[ii].y, adjreg[ii].z, adjreg[ii].w};
            float p[4];
            #pragma unroll
            for (int q = 0; q < 4; ++q) {
                const float xsum = s1 + s2a[q];
                float pv = (xsum > 0.f) ? (E1 * E2a[q]) : (F1 * F2a[q]);
                p[q] = (av[q] > 0) ? pv : 0.f;
            }
            *reinterpret_cast<float4*>(&smPb[i * PP + j4 * 4]) =
                make_float4(p[0], p[1], p[2], p[3]);
        }
        cpa_wait0();
        __syncthreads();
    }

    // ---------------- main pipelined loop ----------------
    for (int tt = 0; tt < NT_; ++tt) {
        const int buf = tt & 1;
        const float* Hc = smHb + buf * HBUF;
        const float* Pc = smPb + buf * PBUF;
        float* Hn = smHb + (buf ^ 1) * HBUF;
        float* Pn = smPb + (buf ^ 1) * PBUF;
        const bool more = (tt + 1 < NT_);

        if (more) {
            const int j0n = jbase + (tt + 1) * TJ;
            #pragma unroll
            for (int q = 0; q < 4; ++q) {
                const int idx = t + q * 256;
                const int row = idx >> 4, c4 = idx & 15;
                cpa16(smaddr(&Hn[row * HP + c4 * 4]),
                      &g_h[(size_t)(nb + j0n + row) * FOUT_ + c4 * 4]);
            }
            cpa_commit();
            #pragma unroll
            for (int ii = 0; ii < 8; ++ii) {
                const int i = ibA + ii * 16;
                adjreg[ii] = *reinterpret_cast<const int4*>(
                    adj + (size_t)(nb + i0 + i) * N_ + j0n + j4 * 4);
            }
            s2v = *reinterpret_cast<const float4*>(&g_s2[nb + j0n + j4 * 4]);
            E2v = *reinterpret_cast<const float4*>(&g_E2[nb + j0n + j4 * 4]);
            F2v = *reinterpret_cast<const float4*>(&g_F2[nb + j0n + j4 * 4]);
        }

        // ---- Phase B: consume tile tt (hides the LDG/cp.async latencies) ----
        #pragma unroll
        for (int k0 = 0; k0 < TJ; k0 += 8) {
            const int ia = w * 16 + grp;
            const unsigned a0 = __float_as_uint(Pc[ ia      * PP + k0 + tig]);
            const unsigned a1 = __float_as_uint(Pc[(ia + 8) * PP + k0 + tig]);
            const unsigned a2 = __float_as_uint(Pc[ ia      * PP + k0 + tig + 4]);
            const unsigned a3 = __float_as_uint(Pc[(ia + 8) * PP + k0 + tig + 4]);
            #pragma unroll
            for (int ng = 0; ng < 9; ++ng) {
                const int f = ng * 8 + grp;
                const unsigned b0 = __float_as_uint(Hc[(k0 + tig)     * HP + f]);
                const unsigned b1 = __float_as_uint(Hc[(k0 + tig + 4) * HP + f]);
                mma_tf32(acc[ng][0], acc[ng][1], acc[ng][2], acc[ng][3],
                         a0, a1, a2, a3, b0, b1);
            }
        }

        // ---- Phase A: produce tile tt+1 ----
        if (more) {
            const float s2a[4] = {s2v.x, s2v.y, s2v.z, s2v.w};
            const float E2a[4] = {E2v.x, E2v.y, E2v.z, E2v.w};
            const float F2a[4] = {F2v.x, F2v.y, F2v.z, F2v.w};
            #pragma unroll
            for (int ii = 0; ii < 8; ++ii) {
                const int i = ibA + ii * 16;
                const float s1 = s_s1[i], E1 = s_E1[i], F1 = s_F1[i];
                const int av[4] = {adjreg[ii].x, adjreg[ii].y, adjreg[ii].z, adjreg[ii].w};
                float p[4];
                #pragma unroll
                for (int q = 0; q < 4; ++q) {
                    const float xsum = s1 + s2a[q];
                    float pv = (xsum > 0.f) ? (E1 * E2a[q]) : (F1 * F2a[q]);
                    p[q] = (av[q] > 0) ? pv : 0.f;
                }
                *reinterpret_cast<float4*>(&Pn[i * PP + j4 * 4]) =
                    make_float4(p[0], p[1], p[2], p[3]);
            }
            cpa_wait0();
        }
        __syncthreads();
    }

    // write partials
    const size_t r0 = (size_t)nb + i0 + w * 16 + grp;
    const size_t r1 = r0 + 8;
    #pragma unroll
    for (int ng = 0; ng < 8; ++ng) {
        const int f = ng * 8 + tig * 2;
        float2* d0 = reinterpret_cast<float2*>(&g_acc[js][r0 * FOUT_ + f]);
        float2* d1 = reinterpret_cast<float2*>(&g_acc[js][r1 * FOUT_ + f]);
        *d0 = make_float2(acc[ng][0], acc[ng][1]);
        *d1 = make_float2(acc[ng][2], acc[ng][3]);
    }
    if (tig == 0) {
        g_l[js][r0] = acc[8][0];
        g_l[js][r1] = acc[8][2];
    }
}

// ============================================================================
// Kernel 3: combine j-splits, normalize, LayerNorm, ELU.
// ============================================================================
__global__ __launch_bounds__(256) void k3_ln(const float* __restrict__ gamma,
                                             const float* __restrict__ beta,
                                             float* __restrict__ out) {
    const int t = threadIdx.x;
    const int warp = t >> 5, lane = t & 31;
    const int row = blockIdx.x * 8 + warp;
    const size_t base = (size_t)row * FOUT_;

    const float v0 = g_acc[0][base + lane]      + g_acc[1][base + lane];
    const float v1 = g_acc[0][base + 32 + lane] + g_acc[1][base + 32 + lane];
    const float l  = g_l[0][row] + g_l[1][row];
    const float inv = 1.f / l;
    const float h0 = v0 * inv, h1 = v1 * inv;

    float s = h0 + h1;
    #pragma unroll
    for (int o = 16; o; o >>= 1) s += __shfl_xor_sync(0xffffffffu, s, o);
    const float mu = s * (1.f / 64.f);

    const float d0 = h0 - mu, d1 = h1 - mu;
    float vs = d0 * d0 + d1 * d1;
    #pragma unroll
    for (int o = 16; o; o >>= 1) vs += __shfl_xor_sync(0xffffffffu, vs, o);
    const float rstd = rsqrtf(vs * (1.f / 64.f) + 1e-5f);

    const float y0 = d0 * rstd * gamma[lane]      + beta[lane];
    const float y1 = d1 * rstd * gamma[lane + 32] + beta[lane + 32];
    out[base + lane]      = (y0 > 0.f) ? y0 : expm1f(y0);
    out[base + 32 + lane] = (y1 > 0.f) ? y1 : expm1f(y1);
}

// ============================================================================
extern "C" void kernel_launch(void* const* d_in, const int* in_sizes, int n_in,
                              void* d_out, int out_size) {
    const float* x     = (const float*)d_in[0];
    const int*   adj   = (const int*)  d_in[1];
    const float* W     = (const float*)d_in[2];
    const float* a     = (const float*)d_in[3];
    const float* gamma = (const float*)d_in[4];
    const float* beta  = (const float*)d_in[5];
    float* out = (float*)d_out;

    const int smem1 = SM1_FLOATS * (int)sizeof(float);   // 50304 B
    const int smem2 = SM2_FLOATS * (int)sizeof(float);   // 108032 B
    cudaFuncSetAttribute(k1_proj, cudaFuncAttributeMaxDynamicSharedMemorySize, smem1);
    cudaFuncSetAttribute(k2_attn, cudaFuncAttributeMaxDynamicSharedMemorySize, smem2);

    k1_proj<<<BN_ / K1ROWS, 128, smem1>>>(x, W, a);
    k2_attn<<<dim3(N_ / TI, B_, JSPLIT), 256, smem2>>>(adj);
    k3_ln<<<BN_ / 8, 256>>>(gamma, beta, out);
}

// round 9
// speedup vs baseline: 3.0047x; 1.4501x over previous
#include <cuda_runtime.h>
#include <cuda_fp16.h>
#include <math.h>

#define B_    8
#define N_    2048
#define FIN_  128
#define FOUT_ 64
#define BN_   (B_ * N_)

#define TI      128
#define TJ      64
#define JSPLIT  2
#define JCHUNK  (N_ / JSPLIT)
#define NT_     (JCHUNK / TJ)          // 16 tiles per block

// ---- k2 smem (fp16 tiles, pitch 72 halves = 144 B -> 16B-aligned rows,
//      row stride = 36 banks = 4 bank-quads mod 32 -> conflict-free ldmatrix)
#define HPH     72
#define HBUFH   (TJ * HPH)             // 4608 halves / buffer
#define PBUFH   (TI * HPH)             // 9216 halves / buffer
#define OFF_PB  (2 * HBUFH)            // halves offset of P buffers
#define SM_S1_BYTE ((2 * HBUFH + 2 * PBUFH) * 2)   // 55296
#define SM2_BYTES  (SM_S1_BYTE + 3 * 128 * 4)      // 56832

// ---- k1 smem (64 rows/block, 2 rows/thread -- proven shape)
#define XPITCH  129
#define K1_OFF_X  (FIN_ * FOUT_)               // 8192
#define K1_OFF_R1 (K1_OFF_X + 64 * XPITCH)
#define K1_OFF_R2 (K1_OFF_R1 + 256)
#define SM1_FLOATS (K1_OFF_R2 + 256)

__device__ __forceinline__ unsigned smaddr(const void* p) {
    return (unsigned)__cvta_generic_to_shared(p);
}
__device__ __forceinline__ void cpa16(unsigned s, const void* g) {
    asm volatile("cp.async.ca.shared.global [%0], [%1], 16;" :: "r"(s), "l"(g));
}
__device__ __forceinline__ void cpa_commit() {
    asm volatile("cp.async.commit_group;" ::: "memory");
}
__device__ __forceinline__ void cpa_wait0() {
    asm volatile("cp.async.wait_group 0;" ::: "memory");
}
__device__ __forceinline__ void ldsm_x4(unsigned& r0, unsigned& r1, unsigned& r2, unsigned& r3,
                                        unsigned addr) {
    asm volatile("ldmatrix.sync.aligned.m8n8.x4.shared.b16 {%0,%1,%2,%3}, [%4];"
                 : "=r"(r0), "=r"(r1), "=r"(r2), "=r"(r3) : "r"(addr));
}
__device__ __forceinline__ void ldsm_x2t(unsigned& r0, unsigned& r1, unsigned addr) {
    asm volatile("ldmatrix.sync.aligned.m8n8.x2.trans.shared.b16 {%0,%1}, [%2];"
                 : "=r"(r0), "=r"(r1) : "r"(addr));
}
__device__ __forceinline__ void mma_f16(float& c0, float& c1, float& c2, float& c3,
                                        unsigned a0, unsigned a1, unsigned a2, unsigned a3,
                                        unsigned b0, unsigned b1) {
    asm("mma.sync.aligned.m16n8k16.row.col.f32.f16.f16.f32 "
        "{%0,%1,%2,%3}, {%4,%5,%6,%7}, {%8,%9}, {%0,%1,%2,%3};"
        : "+f"(c0), "+f"(c1), "+f"(c2), "+f"(c3)
        : "r"(a0), "r"(a1), "r"(a2), "r"(a3), "r"(b0), "r"(b1));
}
__device__ __forceinline__ unsigned h2pack(float a, float b) {
    __half2 v = __floats2half2_rn(a, b);
    return *reinterpret_cast<unsigned*>(&v);
}

// -------- scratch --------
__device__ __half g_hh[BN_ * FOUT_];               // 2 MB : h in fp16
__device__ float g_s1[BN_], g_s2[BN_];
__device__ float g_E1[BN_], g_F1[BN_], g_E2[BN_], g_F2[BN_];
__device__ float g_acc[JSPLIT][BN_ * FOUT_];
__device__ float g_l[JSPLIT][BN_];

// ============================================================================
// Kernel 1: h = x @ W (fp16 out) + s1/s2 dots + per-node exps.
// 256 blocks x 128 threads, 64 rows/block, 2 rows/thread.
// ============================================================================
__global__ __launch_bounds__(128) void k1_proj(const float* __restrict__ x,
                                               const float* __restrict__ W,
                                               const float* __restrict__ a) {
    extern __shared__ float sm1[];
    float* sW  = sm1;
    float* sx  = sm1 + K1_OFF_X;
    float* sr1 = sm1 + K1_OFF_R1;
    float* sr2 = sm1 + K1_OFF_R2;

    const int t = threadIdx.x;
    const int rowbase = blockIdx.x * 64;

    {
        float4*       d = reinterpret_cast<float4*>(sW);
        const float4* s = reinterpret_cast<const float4*>(W);
        #pragma unroll
        for (int q = 0; q < 16; ++q) d[t + q * 128] = s[t + q * 128];
    }
    {
        const float4* s = reinterpret_cast<const float4*>(x);
        #pragma unroll
        for (int q = 0; q < 16; ++q) {
            const int idx = t + q * 128;
            const int row = idx >> 5;
            const int k4  = idx & 31;
            float4 v = s[(size_t)(rowbase + row) * 32 + k4];
            float* dst = &sx[row * XPITCH + k4 * 4];
            dst[0] = v.x; dst[1] = v.y; dst[2] = v.z; dst[3] = v.w;
        }
    }
    __syncthreads();

    const int fg = t >> 5;
    const int rt = t & 31;

    float acc[2][16];
    #pragma unroll
    for (int r = 0; r < 2; ++r)
        #pragma unroll
        for (int c = 0; c < 16; ++c) acc[r][c] = 0.f;

    for (int k4 = 0; k4 < FIN_ / 4; ++k4) {
        float xs[2][4];
        #pragma unroll
        for (int rr = 0; rr < 2; ++rr) {
            const float* xr = &sx[(rt + 32 * rr) * XPITCH + k4 * 4];
            xs[rr][0] = xr[0]; xs[rr][1] = xr[1]; xs[rr][2] = xr[2]; xs[rr][3] = xr[3];
        }
        #pragma unroll
        for (int q = 0; q < 4; ++q) {
            const int k = k4 * 4 + q;
            const float4* wr = reinterpret_cast<const float4*>(&sW[k * FOUT_ + fg * 16]);
            const float4 w0 = wr[0], w1 = wr[1], w2 = wr[2], w3 = wr[3];
            #pragma unroll
            for (int rr = 0; rr < 2; ++rr) {
                const float xv = xs[rr][q];
                acc[rr][0]  += xv * w0.x; acc[rr][1]  += xv * w0.y;
                acc[rr][2]  += xv * w0.z; acc[rr][3]  += xv * w0.w;
                acc[rr][4]  += xv * w1.x; acc[rr][5]  += xv * w1.y;
                acc[rr][6]  += xv * w1.z; acc[rr][7]  += xv * w1.w;
                acc[rr][8]  += xv * w2.x; acc[rr][9]  += xv * w2.y;
                acc[rr][10] += xv * w2.z; acc[rr][11] += xv * w2.w;
                acc[rr][12] += xv * w3.x; acc[rr][13] += xv * w3.y;
                acc[rr][14] += xv * w3.z; acc[rr][15] += xv * w3.w;
            }
        }
    }

    float a1v[16], a2v[16];
    #pragma unroll
    for (int f = 0; f < 16; ++f) {
        a1v[f] = a[fg * 16 + f];
        a2v[f] = a[FOUT_ + fg * 16 + f];
    }
    #pragma unroll
    for (int rr = 0; rr < 2; ++rr) {
        const int rloc = rt + 32 * rr;
        const size_t row = (size_t)rowbase + rloc;
        uint2* hd = reinterpret_cast<uint2*>(&g_hh[row * FOUT_ + fg * 16]);
        #pragma unroll
        for (int f4 = 0; f4 < 4; ++f4) {
            hd[f4] = make_uint2(h2pack(acc[rr][f4 * 4],     acc[rr][f4 * 4 + 1]),
                                h2pack(acc[rr][f4 * 4 + 2], acc[rr][f4 * 4 + 3]));
        }
        float ps1 = 0.f, ps2 = 0.f;
        #pragma unroll
        for (int f = 0; f < 16; ++f) {
            ps1 += acc[rr][f] * a1v[f];
            ps2 += acc[rr][f] * a2v[f];
        }
        sr1[rloc * 4 + fg] = ps1;
        sr2[rloc * 4 + fg] = ps2;
    }
    __syncthreads();
    if (t < 64) {
        const int row = rowbase + t;
        const float s1 = sr1[t * 4] + sr1[t * 4 + 1] + sr1[t * 4 + 2] + sr1[t * 4 + 3];
        const float s2 = sr2[t * 4] + sr2[t * 4 + 1] + sr2[t * 4 + 2] + sr2[t * 4 + 3];
        g_s1[row] = s1;
        g_s2[row] = s2;
        g_E1[row] = expf(s1);
        g_F1[row] = expf(0.2f * s1);
        g_E2[row] = expf(s2);
        g_F2[row] = expf(0.2f * s2);
    }
}

// ============================================================================
// Kernel 2: fused masked attention + aggregation, fp16 mma.m16n8k16 + ldmatrix,
// software-pipelined double buffers.
// ============================================================================
__global__ __launch_bounds__(256, 2) void k2_attn(const int* __restrict__ adj) {
    extern __shared__ __align__(16) char smraw[];
    __half* smHb = reinterpret_cast<__half*>(smraw);            // [2][HBUFH]
    __half* smPb = smHb + OFF_PB;                               // [2][PBUFH]
    float* s_s1 = reinterpret_cast<float*>(smraw + SM_S1_BYTE);
    float* s_E1 = s_s1 + 128;
    float* s_F1 = s_E1 + 128;

    const int t  = threadIdx.x;
    const int b  = blockIdx.y;
    const int i0 = blockIdx.x * TI;
    const int js = blockIdx.z;
    const int jbase = js * JCHUNK;
    const int nb = b * N_;

    if (t < TI) {
        const int g = nb + i0 + t;
        s_s1[t] = g_s1[g]; s_E1[t] = g_E1[g]; s_F1[t] = g_F1[g];
    }
    if (t < 128) {   // ones-column (cols 64..71) for both H buffers
        const int bufi = t >> 6, row = t & 63;
        uint4* dst = reinterpret_cast<uint4*>(&smHb[bufi * HBUFH + row * HPH + 64]);
        *dst = make_uint4(0x00003C00u, 0u, 0u, 0u);   // {fp16(1),0,...,0}
    }

    const int w    = t >> 5;
    const int lane = t & 31;
    const int grp  = lane >> 2;
    const int tig  = lane & 3;
    const int j4   = t & 15;
    const int ibA  = t >> 4;

    // ldmatrix lane-address components (bytes, added to buffer smaddr)
    const int lrow8 = (lane & 7) + ((lane >> 3) & 1) * 8;           // 0..15
    const unsigned aoff = (unsigned)((w * 16 + lrow8) * HPH + (lane >> 4) * 8) * 2;
    const unsigned boff = (unsigned)(lrow8 * HPH) * 2;

    float acc[9][4];
    #pragma unroll
    for (int n = 0; n < 9; ++n)
        #pragma unroll
        for (int c = 0; c < 4; ++c) acc[n][c] = 0.f;

    int4 adjreg[8];
    float4 s2v, E2v, F2v;

    // ---------------- prologue: tile 0 -> buffer 0 ----------------
    {
        const int j0 = jbase;
        #pragma unroll
        for (int q = 0; q < 2; ++q) {     // H(0): 64 rows x 128 B = 512 16B-chunks
            const int idx = t + q * 256;
            const int row = idx >> 3, c8 = idx & 7;
            cpa16(smaddr(&smHb[row * HPH + c8 * 8]),
                  &g_hh[(size_t)(nb + j0 + row) * FOUT_ + c8 * 8]);
        }
        cpa_commit();
        #pragma unroll
        for (int ii = 0; ii < 8; ++ii) {
            const int i = ibA + ii * 16;
            adjreg[ii] = *reinterpret_cast<const int4*>(
                adj + (size_t)(nb + i0 + i) * N_ + j0 + j4 * 4);
        }
        s2v = *reinterpret_cast<const float4*>(&g_s2[nb + j0 + j4 * 4]);
        E2v = *reinterpret_cast<const float4*>(&g_E2[nb + j0 + j4 * 4]);
        F2v = *reinterpret_cast<const float4*>(&g_F2[nb + j0 + j4 * 4]);
        __syncthreads();
        const float s2a[4] = {s2v.x, s2v.y, s2v.z, s2v.w};
        const float E2a[4] = {E2v.x, E2v.y, E2v.z, E2v.w};
        const float F2a[4] = {F2v.x, F2v.y, F2v.z, F2v.w};
        #pragma unroll
        for (int ii = 0; ii < 8; ++ii) {
            const int i = ibA + ii * 16;
            const float s1 = s_s1[i], E1 = s_E1[i], F1 = s_F1[i];
            const int av[4] = {adjreg[ii].x, adjreg[ii].y, adjreg[ii].z, adjreg[ii].w};
            float p[4];
            #pragma unroll
            for (int q = 0; q < 4; ++q) {
                const float xsum = s1 + s2a[q];
                float pv = (xsum > 0.f) ? (E1 * E2a[q]) : (F1 * F2a[q]);
                p[q] = (av[q] > 0) ? pv : 0.f;
            }
            *reinterpret_cast<uint2*>(&smPb[i * HPH + j4 * 4]) =
                make_uint2(h2pack(p[0], p[1]), h2pack(p[2], p[3]));
        }
        cpa_wait0();
        __syncthreads();
    }

    // ---------------- main pipelined loop ----------------
    for (int tt = 0; tt < NT_; ++tt) {
        const int buf = tt & 1;
        const __half* Hc = smHb + buf * HBUFH;
        const __half* Pc = smPb + buf * PBUFH;
        __half* Hn = smHb + (buf ^ 1) * HBUFH;
        __half* Pn = smPb + (buf ^ 1) * PBUFH;
        const bool more = (tt + 1 < NT_);

        if (more) {
            const int j0n = jbase + (tt + 1) * TJ;
            #pragma unroll
            for (int q = 0; q < 2; ++q) {
                const int idx = t + q * 256;
                const int row = idx >> 3, c8 = idx & 7;
                cpa16(smaddr(&Hn[row * HPH + c8 * 8]),
                      &g_hh[(size_t)(nb + j0n + row) * FOUT_ + c8 * 8]);
            }
            cpa_commit();
            #pragma unroll
            for (int ii = 0; ii < 8; ++ii) {
                const int i = ibA + ii * 16;
                adjreg[ii] = *reinterpret_cast<const int4*>(
                    adj + (size_t)(nb + i0 + i) * N_ + j0n + j4 * 4);
            }
            s2v = *reinterpret_cast<const float4*>(&g_s2[nb + j0n + j4 * 4]);
            E2v = *reinterpret_cast<const float4*>(&g_E2[nb + j0n + j4 * 4]);
            F2v = *reinterpret_cast<const float4*>(&g_F2[nb + j0n + j4 * 4]);
        }

        // ---- Phase B: fp16 MMA over tile tt ----
        {
            const unsigned pa = smaddr(Pc) + aoff;
            const unsigned hb = smaddr(Hc) + boff;
            #pragma unroll
            for (int k0 = 0; k0 < TJ; k0 += 16) {
                unsigned a0, a1, a2, a3;
                ldsm_x4(a0, a1, a2, a3, pa + k0 * 2);
                #pragma unroll
                for (int ng = 0; ng < 9; ++ng) {
                    unsigned b0, b1;
                    ldsm_x2t(b0, b1, hb + k0 * (HPH * 2) + ng * 16);
                    mma_f16(acc[ng][0], acc[ng][1], acc[ng][2], acc[ng][3],
                            a0, a1, a2, a3, b0, b1);
                }
            }
        }

        // ---- Phase A: produce tile tt+1 ----
        if (more) {
            const float s2a[4] = {s2v.x, s2v.y, s2v.z, s2v.w};
            const float E2a[4] = {E2v.x, E2v.y, E2v.z, E2v.w};
            const float F2a[4] = {F2v.x, F2v.y, F2v.z, F2v.w};
            #pragma unroll
            for (int ii = 0; ii < 8; ++ii) {
                const int i = ibA + ii * 16;
                const float s1 = s_s1[i], E1 = s_E1[i], F1 = s_F1[i];
                const int av[4] = {adjreg[ii].x, adjreg[ii].y, adjreg[ii].z, adjreg[ii].w};
                float p[4];
                #pragma unroll
                for (int q = 0; q < 4; ++q) {
                    const float xsum = s1 + s2a[q];
                    float pv = (xsum > 0.f) ? (E1 * E2a[q]) : (F1 * F2a[q]);
                    p[q] = (av[q] > 0) ? pv : 0.f;
                }
                *reinterpret_cast<uint2*>(&Pn[i * HPH + j4 * 4]) =
                    make_uint2(h2pack(p[0], p[1]), h2pack(p[2], p[3]));
            }
            cpa_wait0();
        }
        __syncthreads();
    }

    // write partials (C-frag layout: m16n8 f32)
    const size_t r0 = (size_t)nb + i0 + w * 16 + grp;
    const size_t r1 = r0 + 8;
    #pragma unroll
    for (int ng = 0; ng < 8; ++ng) {
        const int f = ng * 8 + tig * 2;
        float2* d0 = reinterpret_cast<float2*>(&g_acc[js][r0 * FOUT_ + f]);
        float2* d1 = reinterpret_cast<float2*>(&g_acc[js][r1 * FOUT_ + f]);
        *d0 = make_float2(acc[ng][0], acc[ng][1]);
        *d1 = make_float2(acc[ng][2], acc[ng][3]);
    }
    if (tig == 0) {
        g_l[js][r0] = acc[8][0];
        g_l[js][r1] = acc[8][2];
    }
}

// ============================================================================
// Kernel 3: combine j-splits, normalize, LayerNorm, ELU.
// ============================================================================
__global__ __launch_bounds__(256) void k3_ln(const float* __restrict__ gamma,
                                             const float* __restrict__ beta,
                                             float* __restrict__ out) {
    const int t = threadIdx.x;
    const int warp = t >> 5, lane = t & 31;
    const int row = blockIdx.x * 8 + warp;
    const size_t base = (size_t)row * FOUT_;

    const float v0 = g_acc[0][base + lane]      + g_acc[1][base + lane];
    const float v1 = g_acc[0][base + 32 + lane] + g_acc[1][base + 32 + lane];
    const float l  = g_l[0][row] + g_l[1][row];
    const float inv = 1.f / l;
    const float h0 = v0 * inv, h1 = v1 * inv;

    float s = h0 + h1;
    #pragma unroll
    for (int o = 16; o; o >>= 1) s += __shfl_xor_sync(0xffffffffu, s, o);
    const float mu = s * (1.f / 64.f);

    const float d0 = h0 - mu, d1 = h1 - mu;
    float vs = d0 * d0 + d1 * d1;
    #pragma unroll
    for (int o = 16; o; o >>= 1) vs += __shfl_xor_sync(0xffffffffu, vs, o);
    const float rstd = rsqrtf(vs * (1.f / 64.f) + 1e-5f);

    const float y0 = d0 * rstd * gamma[lane]      + beta[lane];
    const float y1 = d1 * rstd * gamma[lane + 32] + beta[lane + 32];
    out[base + lane]      = (y0 > 0.f) ? y0 : expm1f(y0);
    out[base + 32 + lane] = (y1 > 0.f) ? y1 : expm1f(y1);
}

// ============================================================================
extern "C" void kernel_launch(void* const* d_in, const int* in_sizes, int n_in,
                              void* d_out, int out_size) {
    const float* x     = (const float*)d_in[0];
    const int*   adj   = (const int*)  d_in[1];
    const float* W     = (const float*)d_in[2];
    const float* a     = (const float*)d_in[3];
    const float* gamma = (const float*)d_in[4];
    const float* beta  = (const float*)d_in[5];
    float* out = (float*)d_out;

    const int smem1 = SM1_FLOATS * (int)sizeof(float);
    const int smem2 = SM2_BYTES;                       // 56832 B
    cudaFuncSetAttribute(k1_proj, cudaFuncAttributeMaxDynamicSharedMemorySize, smem1);
    cudaFuncSetAttribute(k2_attn, cudaFuncAttributeMaxDynamicSharedMemorySize, smem2);

    k1_proj<<<BN_ / 64, 128, smem1>>>(x, W, a);
    k2_attn<<<dim3(N_ / TI, B_, JSPLIT), 256, smem2>>>(adj);
    k3_ln<<<BN_ / 8, 256>>>(gamma, beta, out);
}